// round 4
// baseline (speedup 1.0000x reference)
#include <cuda_runtime.h>
#include <math.h>

#define HH 192
#define WW 192
#define NPIX (HH*WW)        // 36864
#define CC 256
#define EE 294912
#define KK 289
#define SLOPE 0.01f
#define EPSV 1e-5f

// ---------------- scratch (device globals; no allocation) ----------------
__device__ float g_A[CC*NPIX];        // main activation, channel-major [C][N]
__device__ float g_T[CC*NPIX];        // temp
__device__ float g_U[CC*NPIX];        // temp
__device__ float g_h[CC*NPIX];        // dis hidden
__device__ float g_Xrm[NPIX*CC];      // Xn row-major for edge gather
__device__ float g_sig[KK*NPIX];      // signal [K][N]
__device__ float g_Asum[NPIX];
__device__ float g_XA[NPIX*CC];       // row-major scatter target / X_trans
__device__ float g_hid[4*CC*NPIX];    // ffn2 hidden, 1024 channels
__device__ double g_stats[2048];      // per-channel sum (0..1023), sumsq (1024..2047)
__device__ float  g_ss[2048];         // per-channel scale (0..1023), shift (1024..2047)

__device__ __forceinline__ float lk(float x){ return x >= 0.f ? x : SLOPE*x; }

// ---------------- utility kernels ----------------
__global__ void k_zero(float* __restrict__ p, int n){
    int i = blockIdx.x*blockDim.x + threadIdx.x;
    if (i < n) p[i] = 0.f;
}
__global__ void k_zero_stats(){
    int i = threadIdx.x;            // 1024 threads
    g_stats[i] = 0.0; g_stats[i+1024] = 0.0;
}

// BN finalize: scale/shift from stats, reset stats.
__global__ void k_bnfin(const float* __restrict__ g, const float* __restrict__ b, int nch){
    int c = blockIdx.x*blockDim.x + threadIdx.x;
    if (c >= nch) return;
    double s = g_stats[c], s2 = g_stats[1024+c];
    float m   = (float)(s  / (double)NPIX);
    float var = (float)(s2 / (double)NPIX) - m*m;
    float sc  = g[c] * rsqrtf(var + EPSV);
    g_ss[c]      = sc;
    g_ss[1024+c] = b[c] - m*sc;
    g_stats[c] = 0.0; g_stats[1024+c] = 0.0;
}

// (N,C) -> (C,N)
__global__ void k_nc2cn(const float* __restrict__ in, float* __restrict__ out){
    __shared__ float t[32][33];
    int n0 = blockIdx.x*32, c0 = blockIdx.y*32;
    for (int i = threadIdx.y; i < 32; i += 8)
        t[i][threadIdx.x] = in[(size_t)(n0+i)*CC + c0 + threadIdx.x];
    __syncthreads();
    for (int i = threadIdx.y; i < 32; i += 8)
        out[(size_t)(c0+i)*NPIX + n0 + threadIdx.x] = t[threadIdx.x][i];
}
// (C,N) -> (N,C)
__global__ void k_cn2nc(const float* __restrict__ in, float* __restrict__ out){
    __shared__ float t[32][33];
    int n0 = blockIdx.x*32, c0 = blockIdx.y*32;
    for (int i = threadIdx.y; i < 32; i += 8)
        t[i][threadIdx.x] = in[(size_t)(c0+i)*NPIX + n0 + threadIdx.x];
    __syncthreads();
    for (int i = threadIdx.y; i < 32; i += 8)
        out[(size_t)(n0+i)*CC + c0 + threadIdx.x] = t[threadIdx.x][i];
}

// ---------------- depthwise 17x17 (leaky on input), accumulates BN stats ----------------
__global__ void __launch_bounds__(1024) k_dw17(const float* __restrict__ A,
                                               const float* __restrict__ w0,
                                               float* __restrict__ Om){
    __shared__ float sIn[48][48];
    __shared__ float sW[289];
    int c  = blockIdx.z;
    int x0 = blockIdx.x*32, y0 = blockIdx.y*32;
    const float* Ac = A + (size_t)c*NPIX;
    int tid = threadIdx.y*32 + threadIdx.x;
    if (tid < 289) sW[tid] = w0[c*289 + tid];
    for (int i = tid; i < 48*48; i += 1024){
        int ly = i/48, lx = i%48;
        int gx = x0 - 8 + lx, gy = y0 - 8 + ly;
        float v = 0.f;
        if ((unsigned)gx < WW && (unsigned)gy < HH) v = lk(Ac[gy*WW + gx]);
        sIn[ly][lx] = v;
    }
    __syncthreads();
    float acc = 0.f;
    #pragma unroll
    for (int ky = 0; ky < 17; ky++){
        #pragma unroll
        for (int kx = 0; kx < 17; kx++)
            acc += sIn[threadIdx.y+ky][threadIdx.x+kx] * sW[ky*17+kx];
    }
    Om[(size_t)c*NPIX + (y0+threadIdx.y)*WW + x0 + threadIdx.x] = acc;
    float s = acc, s2 = acc*acc;
    #pragma unroll
    for (int o = 16; o > 0; o >>= 1){
        s  += __shfl_down_sync(0xffffffffu, s,  o);
        s2 += __shfl_down_sync(0xffffffffu, s2, o);
    }
    if ((tid & 31) == 0){
        atomicAdd(&g_stats[c],      (double)s);
        atomicAdd(&g_stats[1024+c], (double)s2);
    }
}

// ---------------- depthwise 3x3 with channel multiplier 4 ----------------
__global__ void __launch_bounds__(1024) k_dw3(const float* __restrict__ A,
                                              const float* __restrict__ w0,
                                              float* __restrict__ Om){
    __shared__ float sIn[34][34];
    __shared__ float sW[36];
    int c  = blockIdx.z;
    int x0 = blockIdx.x*32, y0 = blockIdx.y*32;
    const float* Ac = A + (size_t)c*NPIX;
    int tid = threadIdx.y*32 + threadIdx.x;
    if (tid < 36) sW[tid] = w0[c*36 + tid];
    for (int i = tid; i < 34*34; i += 1024){
        int ly = i/34, lx = i%34;
        int gx = x0 - 1 + lx, gy = y0 - 1 + ly;
        float v = 0.f;
        if ((unsigned)gx < WW && (unsigned)gy < HH) v = lk(Ac[gy*WW + gx]);
        sIn[ly][lx] = v;
    }
    __syncthreads();
    float pix[9];
    #pragma unroll
    for (int dy = 0; dy < 3; dy++)
        #pragma unroll
        for (int dx = 0; dx < 3; dx++)
            pix[dy*3+dx] = sIn[threadIdx.y+dy][threadIdx.x+dx];
    int n = (y0+threadIdx.y)*WW + x0 + threadIdx.x;
    #pragma unroll
    for (int j = 0; j < 4; j++){
        float acc = 0.f;
        #pragma unroll
        for (int q = 0; q < 9; q++) acc += pix[q] * sW[j*9+q];
        Om[(size_t)(4*c+j)*NPIX + n] = acc;
        float s = acc, s2 = acc*acc;
        #pragma unroll
        for (int o = 16; o > 0; o >>= 1){
            s  += __shfl_down_sync(0xffffffffu, s,  o);
            s2 += __shfl_down_sync(0xffffffffu, s2, o);
        }
        if ((tid & 31) == 0){
            atomicAdd(&g_stats[4*c+j],      (double)s);
            atomicAdd(&g_stats[1024+4*c+j], (double)s2);
        }
    }
}

// ---------------- SGEMM: Out(M,N) = W(M,Kc) @ A(Kc,N) ----------------
// TRANS: apply per-k-channel scale/shift (from g_ss) to A elements (folded BN)
// INLK : leaky on A elements (after TRANS)
// BIAS : per-row bias on output; OUTLK: leaky on output; STATS: accumulate row stats
template<bool TRANS, bool INLK, bool BIAS, bool OUTLK, bool STATS>
__global__ void __launch_bounds__(256) k_gemm(const float* __restrict__ Wm,
                                              const float* __restrict__ Am,
                                              float* __restrict__ Om,
                                              int M, int Kc,
                                              const float* __restrict__ bias){
    __shared__ float As[16][68];   // [k][m], padded
    __shared__ float Bs[16][64];   // [k][n]
    const int tid = threadIdx.x;
    const int tx = tid & 15, ty = tid >> 4;
    const int m0 = blockIdx.y*64, n0 = blockIdx.x*64;
    const int mW = tid >> 2;            // 0..63
    const int kW = (tid & 3) * 4;       // 0,4,8,12
    const int kA = tid >> 4;            // 0..15
    const int nA = (tid & 15) * 4;
    float acc[4][4] = {};
    for (int k0 = 0; k0 < Kc; k0 += 16){
        float4 wv = make_float4(0.f,0.f,0.f,0.f);
        if (m0 + mW < M)
            wv = *(const float4*)&Wm[(size_t)(m0+mW)*Kc + k0 + kW];
        As[kW+0][mW] = wv.x; As[kW+1][mW] = wv.y;
        As[kW+2][mW] = wv.z; As[kW+3][mW] = wv.w;

        float4 av = *(const float4*)&Am[(size_t)(k0+kA)*NPIX + n0 + nA];
        if (TRANS){
            float sc = g_ss[k0+kA], sh = g_ss[1024+k0+kA];
            av.x = av.x*sc+sh; av.y = av.y*sc+sh; av.z = av.z*sc+sh; av.w = av.w*sc+sh;
        }
        if (INLK){ av.x = lk(av.x); av.y = lk(av.y); av.z = lk(av.z); av.w = lk(av.w); }
        *(float4*)&Bs[kA][nA] = av;
        __syncthreads();
        #pragma unroll
        for (int kk = 0; kk < 16; kk++){
            float4 a = *(const float4*)&As[kk][ty*4];
            float4 b = *(const float4*)&Bs[kk][tx*4];
            acc[0][0] += a.x*b.x; acc[0][1] += a.x*b.y; acc[0][2] += a.x*b.z; acc[0][3] += a.x*b.w;
            acc[1][0] += a.y*b.x; acc[1][1] += a.y*b.y; acc[1][2] += a.y*b.z; acc[1][3] += a.y*b.w;
            acc[2][0] += a.z*b.x; acc[2][1] += a.z*b.y; acc[2][2] += a.z*b.z; acc[2][3] += a.z*b.w;
            acc[3][0] += a.w*b.x; acc[3][1] += a.w*b.y; acc[3][2] += a.w*b.z; acc[3][3] += a.w*b.w;
        }
        __syncthreads();
    }
    #pragma unroll
    for (int i = 0; i < 4; i++){
        int m = m0 + ty*4 + i;
        bool mv = m < M;
        float v0 = acc[i][0], v1 = acc[i][1], v2 = acc[i][2], v3 = acc[i][3];
        if (BIAS){
            float bb = mv ? bias[m] : 0.f;
            v0 += bb; v1 += bb; v2 += bb; v3 += bb;
        }
        if (OUTLK){ v0 = lk(v0); v1 = lk(v1); v2 = lk(v2); v3 = lk(v3); }
        if (mv)
            *(float4*)&Om[(size_t)m*NPIX + n0 + tx*4] = make_float4(v0,v1,v2,v3);
        if (STATS){
            float s  = v0+v1+v2+v3;
            float s2 = v0*v0+v1*v1+v2*v2+v3*v3;
            #pragma unroll
            for (int o = 8; o > 0; o >>= 1){
                s  += __shfl_down_sync(0xffffffffu, s,  o, 16);
                s2 += __shfl_down_sync(0xffffffffu, s2, o, 16);
            }
            if (tx == 0 && mv){
                atomicAdd(&g_stats[m],      (double)s);
                atomicAdd(&g_stats[1024+m], (double)s2);
            }
        }
    }
}

// ---------------- residual: A += U*scale[c]+shift[c] ----------------
__global__ void k_resid(float* __restrict__ A, const float* __restrict__ U){
    int i = blockIdx.x*blockDim.x + threadIdx.x;     // float4 index
    int c = i / (NPIX/4);
    float sc = g_ss[c], sh = g_ss[1024+c];
    float4 u = ((const float4*)U)[i];
    float4 a = ((float4*)A)[i];
    a.x += u.x*sc+sh; a.y += u.y*sc+sh; a.z += u.z*sc+sh; a.w += u.w*sc+sh;
    ((float4*)A)[i] = a;
}

// ---------------- edge kernel: one warp per edge ----------------
// NOTE: InfoIdx is int32 (JAX x64 disabled -> astype(int64) is a no-op to int32)
__global__ void k_edge(const int* __restrict__ info, const float* __restrict__ msk){
    int e = blockIdx.x*8 + (threadIdx.x >> 5);
    if (e >= EE) return;
    int lane = threadIdx.x & 31;
    const int* ip = info + (size_t)e*4;
    int src = ip[0], k1 = ip[1], dst = ip[2], k2 = ip[3];
    float s = g_sig[(size_t)k1*NPIX + src] + g_sig[(size_t)k2*NPIX + dst];
    s = fminf(5.f, fmaxf(-5.f, s));
    float a = expf(s) * msk[e];
    if (a != 0.f){
        const float* xr = g_Xrm + (size_t)src*CC;
        float* xa = g_XA + (size_t)dst*CC;
        #pragma unroll
        for (int c = lane; c < CC; c += 32)
            atomicAdd(&xa[c], xr[c]*a);
        if (lane == 0) atomicAdd(&g_Asum[dst], a);
    }
}

// ---------------- X_trans = XA/(Asum+eps), in place; accumulate bn1d stats ----------------
__global__ void k_xtrans(){
    int c = threadIdx.x;  // 256
    float s = 0.f, s2 = 0.f;
    for (int r = blockIdx.x; r < NPIX; r += gridDim.x){
        float d = g_Asum[r] + 1e-5f;
        float v = g_XA[(size_t)r*CC + c] / d;
        g_XA[(size_t)r*CC + c] = v;
        s += v; s2 += v*v;
    }
    atomicAdd(&g_stats[c],      (double)s);
    atomicAdd(&g_stats[1024+c], (double)s2);
}

// ---------------- A[c][n] += bn(X_trans)[n][c]  (transposed add) ----------------
__global__ void k_transadd(){
    __shared__ float t[32][33];
    int n0 = blockIdx.x*32, c0 = blockIdx.y*32;
    for (int i = threadIdx.y; i < 32; i += 8)
        t[i][threadIdx.x] = g_XA[(size_t)(n0+i)*CC + c0 + threadIdx.x];
    __syncthreads();
    for (int i = threadIdx.y; i < 32; i += 8){
        int c = c0 + i, n = n0 + threadIdx.x;
        g_A[(size_t)c*NPIX + n] += t[threadIdx.x][i]*g_ss[c] + g_ss[1024+c];
    }
}

// ---------------- out[n][c] = bn(T)[c][n] + A[c][n] ----------------
__global__ void k_finalout(float* __restrict__ out){
    __shared__ float t[32][33];
    int n0 = blockIdx.x*32, c0 = blockIdx.y*32;
    for (int i = threadIdx.y; i < 32; i += 8){
        int c = c0 + i, n = n0 + threadIdx.x;
        t[i][threadIdx.x] = g_T[(size_t)c*NPIX + n]*g_ss[c] + g_ss[1024+c]
                          + g_A[(size_t)c*NPIX + n];
    }
    __syncthreads();
    for (int i = threadIdx.y; i < 8; i += 8) ;
    for (int i = threadIdx.y; i < 32; i += 8)
        out[(size_t)(n0+i)*CC + c0 + threadIdx.x] = t[threadIdx.x][i];
}

// ---------------- host ----------------
extern "C" void kernel_launch(void* const* d_in, const int* in_sizes, int n_in,
                              void* d_out, int out_size){
    const float* X      = (const float*)d_in[0];
    const int*   Info   = (const int*)d_in[1];      // int32 (see k_edge note)
    const float* msk    = (const float*)d_in[2];
    const float* ppm_w0 = (const float*)d_in[3];
    const float* ppm_g0 = (const float*)d_in[4];
    const float* ppm_b0 = (const float*)d_in[5];
    const float* ppm_w1 = (const float*)d_in[6];
    const float* ppm_g1 = (const float*)d_in[7];
    const float* ppm_b1 = (const float*)d_in[8];
    const float* f1w0   = (const float*)d_in[9];
    const float* f1g0   = (const float*)d_in[10];
    const float* f1b0   = (const float*)d_in[11];
    const float* f1w1   = (const float*)d_in[12];
    const float* f1g1   = (const float*)d_in[13];
    const float* f1b1   = (const float*)d_in[14];
    const float* dw1    = (const float*)d_in[15];
    const float* db1    = (const float*)d_in[16];
    const float* dw2    = (const float*)d_in[17];
    const float* db2    = (const float*)d_in[18];
    const float* bng    = (const float*)d_in[19];
    const float* bnb    = (const float*)d_in[20];
    const float* f2w0   = (const float*)d_in[21];
    const float* f2g0   = (const float*)d_in[22];
    const float* f2b0   = (const float*)d_in[23];
    const float* f2w1   = (const float*)d_in[24];
    const float* f2g1   = (const float*)d_in[25];
    const float* f2b1   = (const float*)d_in[26];

    float *A,*T,*U,*Hh,*Xrm,*Sig,*Asum,*XA,*Hid;
    cudaGetSymbolAddress((void**)&A,    g_A);
    cudaGetSymbolAddress((void**)&T,    g_T);
    cudaGetSymbolAddress((void**)&U,    g_U);
    cudaGetSymbolAddress((void**)&Hh,   g_h);
    cudaGetSymbolAddress((void**)&Xrm,  g_Xrm);
    cudaGetSymbolAddress((void**)&Sig,  g_sig);
    cudaGetSymbolAddress((void**)&Asum, g_Asum);
    cudaGetSymbolAddress((void**)&XA,   g_XA);
    cudaGetSymbolAddress((void**)&Hid,  g_hid);

    dim3 b32x8(32,8), b1024(32,32);
    dim3 gTile(WW/32, HH/32, CC);          // (6,6,256)
    dim3 gTrans(NPIX/32, CC/32);           // (1152,8)
    dim3 gGemm(NPIX/64, CC/64);            // (576,4)
    dim3 gGemmK(NPIX/64, (KK+63)/64);      // (576,5)

    k_zero_stats<<<1,1024>>>();

    // img = X^T (channel-major)
    k_nc2cn<<<gTrans, b32x8>>>(X, A);

    // ppm: dw17(leaky(img)) -> bn -> 1x1(leaky(bn)) -> bn -> residual
    k_dw17<<<gTile, b1024>>>(A, ppm_w0, T);
    k_bnfin<<<1,256>>>(ppm_g0, ppm_b0, 256);
    k_gemm<true,true,false,false,true><<<gGemm,256>>>(ppm_w1, T, U, 256, 256, nullptr);
    k_bnfin<<<1,256>>>(ppm_g1, ppm_b1, 256);
    k_resid<<<CC*NPIX/4/256,256>>>(A, U);

    // ffn1: 1x1(leaky(img)) -> bn -> 1x1(leaky(bn)) -> bn -> residual
    k_gemm<false,true,false,false,true><<<gGemm,256>>>(f1w0, A, T, 256, 256, nullptr);
    k_bnfin<<<1,256>>>(f1g0, f1b0, 256);
    k_gemm<true,true,false,false,true><<<gGemm,256>>>(f1w1, T, U, 256, 256, nullptr);
    k_bnfin<<<1,256>>>(f1g1, f1b1, 256);
    k_resid<<<CC*NPIX/4/256,256>>>(A, U);      // A = Xn

    // Xn row-major copy for edge gather
    k_cn2nc<<<gTrans, b32x8>>>(A, Xrm);

    // dis: h = leaky(W1 @ Xn + b1); sig = W2 @ h + b2
    k_gemm<false,false,true,true,false><<<gGemm,256>>>(dw1, A, Hh, 256, 256, db1);
    k_gemm<false,false,true,false,false><<<gGemmK,256>>>(dw2, Hh, Sig, KK, 256, db2);

    // edge aggregation
    k_zero<<<(NPIX*CC+255)/256,256>>>(XA, NPIX*CC);
    k_zero<<<(NPIX+255)/256,256>>>(Asum, NPIX);
    k_edge<<<EE/8,256>>>(Info, msk);
    k_xtrans<<<288,256>>>();
    k_bnfin<<<1,256>>>(bng, bnb, 256);
    k_transadd<<<gTrans, b32x8>>>();           // A = Xn + bn1d(X_trans)

    // ffn2: dw3x4(leaky(img)) -> bn -> 1x1 (1024->256, leaky(bn)) -> bn; out = t + img
    k_dw3<<<gTile, b1024>>>(A, f2w0, Hid);
    k_bnfin<<<4,256>>>(f2g0, f2b0, 1024);
    k_gemm<true,true,false,false,true><<<gGemm,256>>>(f2w1, Hid, T, 256, 1024, nullptr);
    k_bnfin<<<1,256>>>(f2g1, f2b1, 256);

    k_finalout<<<gTrans, b32x8>>>((float*)d_out);
}

// round 6
// speedup vs baseline: 1.3495x; 1.3495x over previous
#include <cuda_runtime.h>
#include <math.h>
#include <stdint.h>

#define HH 192
#define WW 192
#define NPIX (HH*WW)        // 36864
#define CC 256
#define EE 294912
#define KK 289
#define SLOPE 0.01f
#define EPSV 1e-5f

// ---------------- scratch (device globals; no allocation) ----------------
__device__ float g_A[CC*NPIX];        // main activation, channel-major [C][N]
__device__ float g_T[CC*NPIX];        // temp
__device__ float g_U[CC*NPIX];        // temp
__device__ float g_h[CC*NPIX];        // dis hidden
__device__ float g_Xrm[NPIX*CC];      // Xn row-major for edge gather
__device__ float g_sig[KK*NPIX];      // signal [K][N]
__device__ float g_Asum[NPIX];
__device__ float g_XA[NPIX*CC];       // row-major scatter target / X_trans
__device__ float g_hid[4*CC*NPIX];    // ffn2 hidden, 1024 channels
__device__ double g_stats[2048];      // per-channel sum (0..1023), sumsq (1024..2047)
__device__ float  g_ss[2048];         // per-channel scale (0..1023), shift (1024..2047)

__device__ __forceinline__ float lk(float x){ return x >= 0.f ? x : SLOPE*x; }
__device__ __forceinline__ uint32_t f2tf(float f){
    uint32_t u; asm("cvt.rna.tf32.f32 %0, %1;" : "=r"(u) : "f"(f)); return u;
}

// ---------------- utility kernels ----------------
__global__ void k_zero(float* __restrict__ p, int n){
    int i = blockIdx.x*blockDim.x + threadIdx.x;
    if (i < n) p[i] = 0.f;
}
__global__ void k_zero_stats(){
    int i = threadIdx.x;            // 1024 threads
    g_stats[i] = 0.0; g_stats[i+1024] = 0.0;
}

// BN finalize: scale/shift from stats, reset stats.
__global__ void k_bnfin(const float* __restrict__ g, const float* __restrict__ b, int nch){
    int c = blockIdx.x*blockDim.x + threadIdx.x;
    if (c >= nch) return;
    double s = g_stats[c], s2 = g_stats[1024+c];
    float m   = (float)(s  / (double)NPIX);
    float var = (float)(s2 / (double)NPIX) - m*m;
    float sc  = g[c] * rsqrtf(var + EPSV);
    g_ss[c]      = sc;
    g_ss[1024+c] = b[c] - m*sc;
    g_stats[c] = 0.0; g_stats[1024+c] = 0.0;
}

// (N,C) -> (C,N)
__global__ void k_nc2cn(const float* __restrict__ in, float* __restrict__ out){
    __shared__ float t[32][33];
    int n0 = blockIdx.x*32, c0 = blockIdx.y*32;
    for (int i = threadIdx.y; i < 32; i += 8)
        t[i][threadIdx.x] = in[(size_t)(n0+i)*CC + c0 + threadIdx.x];
    __syncthreads();
    for (int i = threadIdx.y; i < 32; i += 8)
        out[(size_t)(c0+i)*NPIX + n0 + threadIdx.x] = t[threadIdx.x][i];
}
// (C,N) -> (N,C)
__global__ void k_cn2nc(const float* __restrict__ in, float* __restrict__ out){
    __shared__ float t[32][33];
    int n0 = blockIdx.x*32, c0 = blockIdx.y*32;
    for (int i = threadIdx.y; i < 32; i += 8)
        t[i][threadIdx.x] = in[(size_t)(c0+i)*NPIX + n0 + threadIdx.x];
    __syncthreads();
    for (int i = threadIdx.y; i < 32; i += 8)
        out[(size_t)(n0+i)*CC + c0 + threadIdx.x] = t[threadIdx.x][i];
}

// ---------------- depthwise 17x17 (leaky on input), accumulates BN stats ----------------
__global__ void __launch_bounds__(1024) k_dw17(const float* __restrict__ A,
                                               const float* __restrict__ w0,
                                               float* __restrict__ Om){
    __shared__ float sIn[48][48];
    __shared__ float sW[289];
    int c  = blockIdx.z;
    int x0 = blockIdx.x*32, y0 = blockIdx.y*32;
    const float* Ac = A + (size_t)c*NPIX;
    int tid = threadIdx.y*32 + threadIdx.x;
    if (tid < 289) sW[tid] = w0[c*289 + tid];
    for (int i = tid; i < 48*48; i += 1024){
        int ly = i/48, lx = i%48;
        int gx = x0 - 8 + lx, gy = y0 - 8 + ly;
        float v = 0.f;
        if ((unsigned)gx < WW && (unsigned)gy < HH) v = lk(Ac[gy*WW + gx]);
        sIn[ly][lx] = v;
    }
    __syncthreads();
    float acc = 0.f;
    #pragma unroll
    for (int ky = 0; ky < 17; ky++){
        #pragma unroll
        for (int kx = 0; kx < 17; kx++)
            acc += sIn[threadIdx.y+ky][threadIdx.x+kx] * sW[ky*17+kx];
    }
    Om[(size_t)c*NPIX + (y0+threadIdx.y)*WW + x0 + threadIdx.x] = acc;
    float s = acc, s2 = acc*acc;
    #pragma unroll
    for (int o = 16; o > 0; o >>= 1){
        s  += __shfl_down_sync(0xffffffffu, s,  o);
        s2 += __shfl_down_sync(0xffffffffu, s2, o);
    }
    if ((tid & 31) == 0){
        atomicAdd(&g_stats[c],      (double)s);
        atomicAdd(&g_stats[1024+c], (double)s2);
    }
}

// ---------------- depthwise 3x3 with channel multiplier 4 ----------------
__global__ void __launch_bounds__(1024) k_dw3(const float* __restrict__ A,
                                              const float* __restrict__ w0,
                                              float* __restrict__ Om){
    __shared__ float sIn[34][34];
    __shared__ float sW[36];
    int c  = blockIdx.z;
    int x0 = blockIdx.x*32, y0 = blockIdx.y*32;
    const float* Ac = A + (size_t)c*NPIX;
    int tid = threadIdx.y*32 + threadIdx.x;
    if (tid < 36) sW[tid] = w0[c*36 + tid];
    for (int i = tid; i < 34*34; i += 1024){
        int ly = i/34, lx = i%34;
        int gx = x0 - 1 + lx, gy = y0 - 1 + ly;
        float v = 0.f;
        if ((unsigned)gx < WW && (unsigned)gy < HH) v = lk(Ac[gy*WW + gx]);
        sIn[ly][lx] = v;
    }
    __syncthreads();
    float pix[9];
    #pragma unroll
    for (int dy = 0; dy < 3; dy++)
        #pragma unroll
        for (int dx = 0; dx < 3; dx++)
            pix[dy*3+dx] = sIn[threadIdx.y+dy][threadIdx.x+dx];
    int n = (y0+threadIdx.y)*WW + x0 + threadIdx.x;
    #pragma unroll
    for (int j = 0; j < 4; j++){
        float acc = 0.f;
        #pragma unroll
        for (int q = 0; q < 9; q++) acc += pix[q] * sW[j*9+q];
        Om[(size_t)(4*c+j)*NPIX + n] = acc;
        float s = acc, s2 = acc*acc;
        #pragma unroll
        for (int o = 16; o > 0; o >>= 1){
            s  += __shfl_down_sync(0xffffffffu, s,  o);
            s2 += __shfl_down_sync(0xffffffffu, s2, o);
        }
        if ((tid & 31) == 0){
            atomicAdd(&g_stats[4*c+j],      (double)s);
            atomicAdd(&g_stats[1024+4*c+j], (double)s2);
        }
    }
}

// ---------------- TF32 tensor-core GEMM: Out(M,N) = W(M,Kc) @ A(Kc,N) ----------------
// Block 128x128, k-step 16. 8 warps: warp tile 64(m) x 32(n), mma m16n8k8.
// TRANS: fold per-k-channel scale/shift (g_ss) into A elements; INLK: leaky after TRANS.
// BIAS/OUTLK on output; STATS: accumulate per-row sum/sumsq into g_stats.
#define MMA_TF32(d, a, b) asm volatile( \
  "mma.sync.aligned.m16n8k8.row.col.f32.tf32.tf32.f32 " \
  "{%0,%1,%2,%3}, {%4,%5,%6,%7}, {%8,%9}, {%0,%1,%2,%3};" \
  : "+f"(d[0]), "+f"(d[1]), "+f"(d[2]), "+f"(d[3]) \
  : "r"(a[0]), "r"(a[1]), "r"(a[2]), "r"(a[3]), "r"(b[0]), "r"(b[1]))

#define AS_STRIDE 20   // 16 + 4 pad: frag-load banks all distinct
#define BS_STRIDE 136  // 128 + 8 pad: frag-load banks all distinct

template<bool TRANS, bool INLK, bool BIAS, bool OUTLK, bool STATS>
__global__ void __launch_bounds__(256) k_mma(const float* __restrict__ Wm,
                                             const float* __restrict__ Am,
                                             float* __restrict__ Om,
                                             int M, int Kc,
                                             const float* __restrict__ bias){
    __shared__ __align__(16) uint32_t As[128*AS_STRIDE];
    __shared__ __align__(16) uint32_t Bs[16*BS_STRIDE];
    const int tid  = threadIdx.x;
    const int lane = tid & 31;
    const int wid  = tid >> 5;
    const int gid  = lane >> 2, ctg = lane & 3;
    const int wm   = wid & 1,  wn  = wid >> 1;      // wm:0..1, wn:0..3
    const int m0 = blockIdx.y*128, n0 = blockIdx.x*128;

    const int mA  = tid >> 1;          // 0..127 (A row loaded by this thread)
    const int kqA = (tid & 1)*8;       // 0 or 8
    const int kB  = wid;               // 0..7 (B rows kB, kB+8)
    const int nB  = lane*4;

    float acc[4][4][4];
    #pragma unroll
    for (int i = 0; i < 4; i++)
        #pragma unroll
        for (int j = 0; j < 4; j++)
            #pragma unroll
            for (int q = 0; q < 4; q++) acc[i][j][q] = 0.f;

    for (int k0 = 0; k0 < Kc; k0 += 16){
        // --- load W tile -> As [m][k], tf32 ---
        float4 w0v = make_float4(0.f,0.f,0.f,0.f), w1v = w0v;
        if (m0 + mA < M){
            const float* wp = &Wm[(size_t)(m0+mA)*Kc + k0 + kqA];
            w0v = *(const float4*)wp;
            w1v = *(const float4*)(wp+4);
        }
        {
            uint4 u0 = make_uint4(f2tf(w0v.x), f2tf(w0v.y), f2tf(w0v.z), f2tf(w0v.w));
            uint4 u1 = make_uint4(f2tf(w1v.x), f2tf(w1v.y), f2tf(w1v.z), f2tf(w1v.w));
            *(uint4*)&As[mA*AS_STRIDE + kqA]     = u0;
            *(uint4*)&As[mA*AS_STRIDE + kqA + 4] = u1;
        }
        // --- load act tile -> Bs [k][n], tf32, fused BN-fold + leaky ---
        #pragma unroll
        for (int rr = 0; rr < 2; rr++){
            int r = kB + rr*8;
            float4 av = *(const float4*)&Am[(size_t)(k0+r)*NPIX + n0 + nB];
            if (TRANS){
                float sc = g_ss[k0+r], sh = g_ss[1024+k0+r];
                av.x = av.x*sc+sh; av.y = av.y*sc+sh; av.z = av.z*sc+sh; av.w = av.w*sc+sh;
            }
            if (INLK){ av.x = lk(av.x); av.y = lk(av.y); av.z = lk(av.z); av.w = lk(av.w); }
            *(uint4*)&Bs[r*BS_STRIDE + nB] =
                make_uint4(f2tf(av.x), f2tf(av.y), f2tf(av.z), f2tf(av.w));
        }
        __syncthreads();
        // --- compute ---
        #pragma unroll
        for (int ks = 0; ks < 16; ks += 8){
            uint32_t a[4][4], b[4][2];
            #pragma unroll
            for (int mi = 0; mi < 4; mi++){
                int rb = wm*64 + mi*16 + gid;
                a[mi][0] = As[rb*AS_STRIDE     + ks+ctg];
                a[mi][1] = As[(rb+8)*AS_STRIDE + ks+ctg];
                a[mi][2] = As[rb*AS_STRIDE     + ks+ctg+4];
                a[mi][3] = As[(rb+8)*AS_STRIDE + ks+ctg+4];
            }
            #pragma unroll
            for (int ni = 0; ni < 4; ni++){
                int cb = wn*32 + ni*8 + gid;
                b[ni][0] = Bs[(ks+ctg)*BS_STRIDE   + cb];
                b[ni][1] = Bs[(ks+ctg+4)*BS_STRIDE + cb];
            }
            #pragma unroll
            for (int mi = 0; mi < 4; mi++)
                #pragma unroll
                for (int ni = 0; ni < 4; ni++)
                    MMA_TF32(acc[mi][ni], a[mi], b[ni]);
        }
        __syncthreads();
    }

    // --- epilogue ---
    #pragma unroll
    for (int mi = 0; mi < 4; mi++){
        int r0 = m0 + wm*64 + mi*16 + gid;
        int r1 = r0 + 8;
        bool v0r = r0 < M, v1r = r1 < M;
        float b0 = 0.f, b1 = 0.f;
        if (BIAS){ if (v0r) b0 = bias[r0]; if (v1r) b1 = bias[r1]; }
        float s0 = 0.f, q0 = 0.f, s1 = 0.f, q1 = 0.f;
        #pragma unroll
        for (int ni = 0; ni < 4; ni++){
            int cix = n0 + wn*32 + ni*8 + 2*ctg;
            float v0 = acc[mi][ni][0], v1 = acc[mi][ni][1];
            float v2 = acc[mi][ni][2], v3 = acc[mi][ni][3];
            if (BIAS){ v0 += b0; v1 += b0; v2 += b1; v3 += b1; }
            if (OUTLK){ v0 = lk(v0); v1 = lk(v1); v2 = lk(v2); v3 = lk(v3); }
            if (v0r) *(float2*)&Om[(size_t)r0*NPIX + cix] = make_float2(v0, v1);
            if (v1r) *(float2*)&Om[(size_t)r1*NPIX + cix] = make_float2(v2, v3);
            if (STATS){
                s0 += v0+v1; q0 += v0*v0+v1*v1;
                s1 += v2+v3; q1 += v2*v2+v3*v3;
            }
        }
        if (STATS){
            s0 += __shfl_down_sync(0xffffffffu, s0, 2, 4); s0 += __shfl_down_sync(0xffffffffu, s0, 1, 4);
            q0 += __shfl_down_sync(0xffffffffu, q0, 2, 4); q0 += __shfl_down_sync(0xffffffffu, q0, 1, 4);
            s1 += __shfl_down_sync(0xffffffffu, s1, 2, 4); s1 += __shfl_down_sync(0xffffffffu, s1, 1, 4);
            q1 += __shfl_down_sync(0xffffffffu, q1, 2, 4); q1 += __shfl_down_sync(0xffffffffu, q1, 1, 4);
            if (ctg == 0){
                if (v0r){ atomicAdd(&g_stats[r0], (double)s0); atomicAdd(&g_stats[1024+r0], (double)q0); }
                if (v1r){ atomicAdd(&g_stats[r1], (double)s1); atomicAdd(&g_stats[1024+r1], (double)q1); }
            }
        }
    }
}

// ---------------- residual: A += U*scale[c]+shift[c] ----------------
__global__ void k_resid(float* __restrict__ A, const float* __restrict__ U){
    int i = blockIdx.x*blockDim.x + threadIdx.x;     // float4 index
    int c = i / (NPIX/4);
    float sc = g_ss[c], sh = g_ss[1024+c];
    float4 u = ((const float4*)U)[i];
    float4 a = ((float4*)A)[i];
    a.x += u.x*sc+sh; a.y += u.y*sc+sh; a.z += u.z*sc+sh; a.w += u.w*sc+sh;
    ((float4*)A)[i] = a;
}

// ---------------- edge kernel: one warp per edge ----------------
// NOTE: InfoIdx is int32 (JAX x64 disabled -> astype(int64) is a no-op to int32)
__global__ void k_edge(const int* __restrict__ info, const float* __restrict__ msk){
    int e = blockIdx.x*8 + (threadIdx.x >> 5);
    if (e >= EE) return;
    int lane = threadIdx.x & 31;
    const int* ip = info + (size_t)e*4;
    int src = ip[0], k1 = ip[1], dst = ip[2], k2 = ip[3];
    float s = g_sig[(size_t)k1*NPIX + src] + g_sig[(size_t)k2*NPIX + dst];
    s = fminf(5.f, fmaxf(-5.f, s));
    float a = expf(s) * msk[e];
    if (a != 0.f){
        const float* xr = g_Xrm + (size_t)src*CC;
        float* xa = g_XA + (size_t)dst*CC;
        #pragma unroll
        for (int c = lane; c < CC; c += 32)
            atomicAdd(&xa[c], xr[c]*a);
        if (lane == 0) atomicAdd(&g_Asum[dst], a);
    }
}

// ---------------- X_trans = XA/(Asum+eps), in place; accumulate bn1d stats ----------------
__global__ void k_xtrans(){
    int c = threadIdx.x;  // 256
    float s = 0.f, s2 = 0.f;
    for (int r = blockIdx.x; r < NPIX; r += gridDim.x){
        float d = g_Asum[r] + 1e-5f;
        float v = g_XA[(size_t)r*CC + c] / d;
        g_XA[(size_t)r*CC + c] = v;
        s += v; s2 += v*v;
    }
    atomicAdd(&g_stats[c],      (double)s);
    atomicAdd(&g_stats[1024+c], (double)s2);
}

// ---------------- A[c][n] += bn(X_trans)[n][c]  (transposed add) ----------------
__global__ void k_transadd(){
    __shared__ float t[32][33];
    int n0 = blockIdx.x*32, c0 = blockIdx.y*32;
    for (int i = threadIdx.y; i < 32; i += 8)
        t[i][threadIdx.x] = g_XA[(size_t)(n0+i)*CC + c0 + threadIdx.x];
    __syncthreads();
    for (int i = threadIdx.y; i < 32; i += 8){
        int c = c0 + i, n = n0 + threadIdx.x;
        g_A[(size_t)c*NPIX + n] += t[threadIdx.x][i]*g_ss[c] + g_ss[1024+c];
    }
}

// ---------------- out[n][c] = bn(T)[c][n] + A[c][n] ----------------
__global__ void k_finalout(float* __restrict__ out){
    __shared__ float t[32][33];
    int n0 = blockIdx.x*32, c0 = blockIdx.y*32;
    for (int i = threadIdx.y; i < 32; i += 8){
        int c = c0 + i, n = n0 + threadIdx.x;
        t[i][threadIdx.x] = g_T[(size_t)c*NPIX + n]*g_ss[c] + g_ss[1024+c]
                          + g_A[(size_t)c*NPIX + n];
    }
    __syncthreads();
    for (int i = threadIdx.y; i < 32; i += 8)
        out[(size_t)(n0+i)*CC + c0 + threadIdx.x] = t[threadIdx.x][i];
}

// ---------------- host ----------------
extern "C" void kernel_launch(void* const* d_in, const int* in_sizes, int n_in,
                              void* d_out, int out_size){
    const float* X      = (const float*)d_in[0];
    const int*   Info   = (const int*)d_in[1];      // int32 (see k_edge note)
    const float* msk    = (const float*)d_in[2];
    const float* ppm_w0 = (const float*)d_in[3];
    const float* ppm_g0 = (const float*)d_in[4];
    const float* ppm_b0 = (const float*)d_in[5];
    const float* ppm_w1 = (const float*)d_in[6];
    const float* ppm_g1 = (const float*)d_in[7];
    const float* ppm_b1 = (const float*)d_in[8];
    const float* f1w0   = (const float*)d_in[9];
    const float* f1g0   = (const float*)d_in[10];
    const float* f1b0   = (const float*)d_in[11];
    const float* f1w1   = (const float*)d_in[12];
    const float* f1g1   = (const float*)d_in[13];
    const float* f1b1   = (const float*)d_in[14];
    const float* dw1    = (const float*)d_in[15];
    const float* db1    = (const float*)d_in[16];
    const float* dw2    = (const float*)d_in[17];
    const float* db2    = (const float*)d_in[18];
    const float* bng    = (const float*)d_in[19];
    const float* bnb    = (const float*)d_in[20];
    const float* f2w0   = (const float*)d_in[21];
    const float* f2g0   = (const float*)d_in[22];
    const float* f2b0   = (const float*)d_in[23];
    const float* f2w1   = (const float*)d_in[24];
    const float* f2g1   = (const float*)d_in[25];
    const float* f2b1   = (const float*)d_in[26];

    float *A,*T,*U,*Hh,*Xrm,*Sig,*Asum,*XA,*Hid;
    cudaGetSymbolAddress((void**)&A,    g_A);
    cudaGetSymbolAddress((void**)&T,    g_T);
    cudaGetSymbolAddress((void**)&U,    g_U);
    cudaGetSymbolAddress((void**)&Hh,   g_h);
    cudaGetSymbolAddress((void**)&Xrm,  g_Xrm);
    cudaGetSymbolAddress((void**)&Sig,  g_sig);
    cudaGetSymbolAddress((void**)&Asum, g_Asum);
    cudaGetSymbolAddress((void**)&XA,   g_XA);
    cudaGetSymbolAddress((void**)&Hid,  g_hid);

    dim3 b32x8(32,8), b1024(32,32);
    dim3 gTile(WW/32, HH/32, CC);          // (6,6,256)
    dim3 gTrans(NPIX/32, CC/32);           // (1152,8)
    dim3 gM(NPIX/128, 2);                  // (288,2)  M=256
    dim3 gMK(NPIX/128, 3);                 // (288,3)  M=289

    k_zero_stats<<<1,1024>>>();

    // img = X^T (channel-major)
    k_nc2cn<<<gTrans, b32x8>>>(X, A);

    // ppm: dw17(leaky(img)) -> bn -> 1x1(leaky(bn)) -> bn -> residual
    k_dw17<<<gTile, b1024>>>(A, ppm_w0, T);
    k_bnfin<<<1,256>>>(ppm_g0, ppm_b0, 256);
    k_mma<true,true,false,false,true><<<gM,256>>>(ppm_w1, T, U, 256, 256, nullptr);
    k_bnfin<<<1,256>>>(ppm_g1, ppm_b1, 256);
    k_resid<<<CC*NPIX/4/256,256>>>(A, U);

    // ffn1: 1x1(leaky(img)) -> bn -> 1x1(leaky(bn)) -> bn -> residual
    k_mma<false,true,false,false,true><<<gM,256>>>(f1w0, A, T, 256, 256, nullptr);
    k_bnfin<<<1,256>>>(f1g0, f1b0, 256);
    k_mma<true,true,false,false,true><<<gM,256>>>(f1w1, T, U, 256, 256, nullptr);
    k_bnfin<<<1,256>>>(f1g1, f1b1, 256);
    k_resid<<<CC*NPIX/4/256,256>>>(A, U);      // A = Xn

    // Xn row-major copy for edge gather
    k_cn2nc<<<gTrans, b32x8>>>(A, Xrm);

    // dis: h = leaky(W1 @ Xn + b1); sig = W2 @ h + b2
    k_mma<false,false,true,true,false><<<gM,256>>>(dw1, A, Hh, 256, 256, db1);
    k_mma<false,false,true,false,false><<<gMK,256>>>(dw2, Hh, Sig, KK, 256, db2);

    // edge aggregation
    k_zero<<<(NPIX*CC+255)/256,256>>>(XA, NPIX*CC);
    k_zero<<<(NPIX+255)/256,256>>>(Asum, NPIX);
    k_edge<<<EE/8,256>>>(Info, msk);
    k_xtrans<<<288,256>>>();
    k_bnfin<<<1,256>>>(bng, bnb, 256);
    k_transadd<<<gTrans, b32x8>>>();           // A = Xn + bn1d(X_trans)

    // ffn2: dw3x4(leaky(img)) -> bn -> 1x1 (1024->256, leaky(bn)) -> bn; out = t + img
    k_dw3<<<gTile, b1024>>>(A, f2w0, Hid);
    k_bnfin<<<4,256>>>(f2g0, f2b0, 1024);
    k_mma<true,true,false,false,true><<<gM,256>>>(f2w1, Hid, T, 256, 1024, nullptr);
    k_bnfin<<<1,256>>>(f2g1, f2b1, 256);

    k_finalout<<<gTrans, b32x8>>>((float*)d_out);
}

// round 9
// speedup vs baseline: 1.7783x; 1.3178x over previous
#include <cuda_runtime.h>
#include <math.h>
#include <stdint.h>

#define HH 192
#define WW 192
#define NPIX (HH*WW)        // 36864
#define CC 256
#define EE 294912
#define KK 289
#define SLOPE 0.01f
#define EPSV 1e-5f

// ---------------- scratch (device globals; no allocation) ----------------
__device__ float g_A[CC*NPIX];        // main activation, channel-major [C][N]
__device__ float g_T[CC*NPIX];        // temp
__device__ float g_U[CC*NPIX];        // temp
__device__ float g_h[CC*NPIX];        // dis hidden
__device__ float g_Xrm[NPIX*CC];      // Xn row-major for edge gather
__device__ float g_sig[KK*NPIX];      // signal [K][N]
__device__ float g_Asum[NPIX];
__device__ float g_XA[NPIX*CC];       // row-major scatter target / X_trans
__device__ float g_hid[4*CC*NPIX];    // ffn2 hidden, 1024 channels
__device__ double g_stats[2048];      // per-channel sum (0..1023), sumsq (1024..2047)
__device__ float  g_ss[2048];         // per-channel scale (0..1023), shift (1024..2047)

__device__ __forceinline__ float lk(float x){ return x >= 0.f ? x : SLOPE*x; }
__device__ __forceinline__ uint32_t f2tf(float f){
    uint32_t u; asm("cvt.rna.tf32.f32 %0, %1;" : "=r"(u) : "f"(f)); return u;
}

// ---------------- utility kernels ----------------
__global__ void k_zero(float* __restrict__ p, int n){
    int i = blockIdx.x*blockDim.x + threadIdx.x;
    if (i < n) p[i] = 0.f;
}
__global__ void k_zero_stats(){
    int i = threadIdx.x;            // 1024 threads
    g_stats[i] = 0.0; g_stats[i+1024] = 0.0;
}

// BN finalize: scale/shift from stats, reset stats.
__global__ void k_bnfin(const float* __restrict__ g, const float* __restrict__ b, int nch){
    int c = blockIdx.x*blockDim.x + threadIdx.x;
    if (c >= nch) return;
    double s = g_stats[c], s2 = g_stats[1024+c];
    float m   = (float)(s  / (double)NPIX);
    float var = (float)(s2 / (double)NPIX) - m*m;
    float sc  = g[c] * rsqrtf(var + EPSV);
    g_ss[c]      = sc;
    g_ss[1024+c] = b[c] - m*sc;
    g_stats[c] = 0.0; g_stats[1024+c] = 0.0;
}

// (N,C) -> (C,N)
__global__ void k_nc2cn(const float* __restrict__ in, float* __restrict__ out){
    __shared__ float t[32][33];
    int n0 = blockIdx.x*32, c0 = blockIdx.y*32;
    for (int i = threadIdx.y; i < 32; i += 8)
        t[i][threadIdx.x] = in[(size_t)(n0+i)*CC + c0 + threadIdx.x];
    __syncthreads();
    for (int i = threadIdx.y; i < 32; i += 8)
        out[(size_t)(c0+i)*NPIX + n0 + threadIdx.x] = t[threadIdx.x][i];
}
// (C,N) -> (N,C)
__global__ void k_cn2nc(const float* __restrict__ in, float* __restrict__ out){
    __shared__ float t[32][33];
    int n0 = blockIdx.x*32, c0 = blockIdx.y*32;
    for (int i = threadIdx.y; i < 32; i += 8)
        t[i][threadIdx.x] = in[(size_t)(c0+i)*NPIX + n0 + threadIdx.x];
    __syncthreads();
    for (int i = threadIdx.y; i < 32; i += 8)
        out[(size_t)(n0+i)*CC + c0 + threadIdx.x] = t[threadIdx.x][i];
}

// ---------------- depthwise 17x17, 4 outputs/thread, accumulates BN stats ----------------
// block (16,32)=512 threads; output tile 64(x) x 32(y); each thread 4 x-consecutive outputs
__global__ void __launch_bounds__(512) k_dw17(const float* __restrict__ A,
                                              const float* __restrict__ w0,
                                              float* __restrict__ Om){
    __shared__ float sIn[48][80];
    __shared__ float sW[289];
    __shared__ float sRedS[16], sRedQ[16];
    int c  = blockIdx.z;
    int x0 = blockIdx.x*64, y0 = blockIdx.y*32;
    const float* Ac = A + (size_t)c*NPIX;
    int tx = threadIdx.x, ty = threadIdx.y;
    int tid = ty*16 + tx;
    if (tid < 289) sW[tid] = w0[c*289 + tid];
    for (int i = tid; i < 48*80; i += 512){
        int ly = i/80, lx = i%80;
        int gx = x0 - 8 + lx, gy = y0 - 8 + ly;
        float v = 0.f;
        if ((unsigned)gx < WW && (unsigned)gy < HH) v = lk(Ac[gy*WW + gx]);
        sIn[ly][lx] = v;
    }
    __syncthreads();
    float a0 = 0.f, a1 = 0.f, a2 = 0.f, a3 = 0.f;
    #pragma unroll
    for (int ky = 0; ky < 17; ky++){
        const float* rp = &sIn[ty+ky][tx*4];
        float v[20];
        #pragma unroll
        for (int q = 0; q < 5; q++) *(float4*)&v[q*4] = *(const float4*)&rp[q*4];
        #pragma unroll
        for (int kx = 0; kx < 17; kx++){
            float w = sW[ky*17+kx];
            a0 += v[kx]*w; a1 += v[kx+1]*w; a2 += v[kx+2]*w; a3 += v[kx+3]*w;
        }
    }
    int n = (y0+ty)*WW + x0 + tx*4;
    *(float4*)&Om[(size_t)c*NPIX + n] = make_float4(a0,a1,a2,a3);
    float s  = a0+a1+a2+a3;
    float s2 = a0*a0+a1*a1+a2*a2+a3*a3;
    #pragma unroll
    for (int o = 16; o > 0; o >>= 1){
        s  += __shfl_down_sync(0xffffffffu, s,  o);
        s2 += __shfl_down_sync(0xffffffffu, s2, o);
    }
    if ((tid & 31) == 0){ sRedS[tid>>5] = s; sRedQ[tid>>5] = s2; }
    __syncthreads();
    if (tid < 16){
        s = sRedS[tid]; s2 = sRedQ[tid];
        #pragma unroll
        for (int o = 8; o > 0; o >>= 1){
            s  += __shfl_down_sync(0xffffu, s,  o, 16);
            s2 += __shfl_down_sync(0xffffu, s2, o, 16);
        }
        if (tid == 0){
            atomicAdd(&g_stats[c],      (double)s);
            atomicAdd(&g_stats[1024+c], (double)s2);
        }
    }
}

// ---------------- depthwise 3x3 with channel multiplier 4 ----------------
__global__ void __launch_bounds__(1024) k_dw3(const float* __restrict__ A,
                                              const float* __restrict__ w0,
                                              float* __restrict__ Om){
    __shared__ float sIn[34][34];
    __shared__ float sW[36];
    int c  = blockIdx.z;
    int x0 = blockIdx.x*32, y0 = blockIdx.y*32;
    const float* Ac = A + (size_t)c*NPIX;
    int tid = threadIdx.y*32 + threadIdx.x;
    if (tid < 36) sW[tid] = w0[c*36 + tid];
    for (int i = tid; i < 34*34; i += 1024){
        int ly = i/34, lx = i%34;
        int gx = x0 - 1 + lx, gy = y0 - 1 + ly;
        float v = 0.f;
        if ((unsigned)gx < WW && (unsigned)gy < HH) v = lk(Ac[gy*WW + gx]);
        sIn[ly][lx] = v;
    }
    __syncthreads();
    float pix[9];
    #pragma unroll
    for (int dy = 0; dy < 3; dy++)
        #pragma unroll
        for (int dx = 0; dx < 3; dx++)
            pix[dy*3+dx] = sIn[threadIdx.y+dy][threadIdx.x+dx];
    int n = (y0+threadIdx.y)*WW + x0 + threadIdx.x;
    #pragma unroll
    for (int j = 0; j < 4; j++){
        float acc = 0.f;
        #pragma unroll
        for (int q = 0; q < 9; q++) acc += pix[q] * sW[j*9+q];
        Om[(size_t)(4*c+j)*NPIX + n] = acc;
        float s = acc, s2 = acc*acc;
        #pragma unroll
        for (int o = 16; o > 0; o >>= 1){
            s  += __shfl_down_sync(0xffffffffu, s,  o);
            s2 += __shfl_down_sync(0xffffffffu, s2, o);
        }
        if ((tid & 31) == 0){
            atomicAdd(&g_stats[4*c+j],      (double)s);
            atomicAdd(&g_stats[1024+4*c+j], (double)s2);
        }
    }
}

// ---------------- TF32 tensor-core GEMM, double-buffered ----------------
// Out(M,N) = W(M,Kc) @ A(Kc,N). Block 128x128, k-step 16, 8 warps 64x32, mma m16n8k8.
#define MMA_TF32(d, a, b) asm volatile( \
  "mma.sync.aligned.m16n8k8.row.col.f32.tf32.tf32.f32 " \
  "{%0,%1,%2,%3}, {%4,%5,%6,%7}, {%8,%9}, {%0,%1,%2,%3};" \
  : "+f"(d[0]), "+f"(d[1]), "+f"(d[2]), "+f"(d[3]) \
  : "r"(a[0]), "r"(a[1]), "r"(a[2]), "r"(a[3]), "r"(b[0]), "r"(b[1]))

#define AS_STRIDE 20   // 16 + 4 pad
#define BS_STRIDE 136  // 128 + 8 pad

template<bool TRANS, bool INLK, bool BIAS, bool OUTLK, bool STATS>
__global__ void __launch_bounds__(256,2) k_mma(const float* __restrict__ Wm,
                                               const float* __restrict__ Am,
                                               float* __restrict__ Om,
                                               int M, int Kc,
                                               const float* __restrict__ bias){
    __shared__ __align__(16) uint32_t As[2][128*AS_STRIDE];
    __shared__ __align__(16) uint32_t Bs[2][16*BS_STRIDE];
    const int tid  = threadIdx.x;
    const int lane = tid & 31;
    const int wid  = tid >> 5;
    const int gid  = lane >> 2, ctg = lane & 3;
    const int wm   = wid & 1,  wn  = wid >> 1;
    const int m0 = blockIdx.y*128, n0 = blockIdx.x*128;

    const int mA  = tid >> 1;          // 0..127
    const int kqA = (tid & 1)*8;       // 0 or 8
    const int kB  = wid;               // 0..7
    const int nB  = lane*4;

    float acc[4][4][4];
    #pragma unroll
    for (int i = 0; i < 4; i++)
        #pragma unroll
        for (int j = 0; j < 4; j++)
            #pragma unroll
            for (int q = 0; q < 4; q++) acc[i][j][q] = 0.f;

    float4 wa, wb, ba, bb;

    auto LOAD = [&](int k0){
        wa = make_float4(0.f,0.f,0.f,0.f); wb = wa;
        if (m0 + mA < M){
            const float* wp = &Wm[(size_t)(m0+mA)*Kc + k0 + kqA];
            wa = *(const float4*)wp;
            wb = *(const float4*)(wp+4);
        }
        ba = *(const float4*)&Am[(size_t)(k0+kB)*NPIX   + n0 + nB];
        bb = *(const float4*)&Am[(size_t)(k0+kB+8)*NPIX + n0 + nB];
    };
    auto STORE = [&](int p, int k0){
        *(uint4*)&As[p][mA*AS_STRIDE + kqA] =
            make_uint4(f2tf(wa.x), f2tf(wa.y), f2tf(wa.z), f2tf(wa.w));
        *(uint4*)&As[p][mA*AS_STRIDE + kqA + 4] =
            make_uint4(f2tf(wb.x), f2tf(wb.y), f2tf(wb.z), f2tf(wb.w));
        float4 v0 = ba, v1 = bb;
        if (TRANS){
            float sc0 = g_ss[k0+kB],   sh0 = g_ss[1024+k0+kB];
            float sc1 = g_ss[k0+kB+8], sh1 = g_ss[1024+k0+kB+8];
            v0.x = v0.x*sc0+sh0; v0.y = v0.y*sc0+sh0; v0.z = v0.z*sc0+sh0; v0.w = v0.w*sc0+sh0;
            v1.x = v1.x*sc1+sh1; v1.y = v1.y*sc1+sh1; v1.z = v1.z*sc1+sh1; v1.w = v1.w*sc1+sh1;
        }
        if (INLK){
            v0.x = lk(v0.x); v0.y = lk(v0.y); v0.z = lk(v0.z); v0.w = lk(v0.w);
            v1.x = lk(v1.x); v1.y = lk(v1.y); v1.z = lk(v1.z); v1.w = lk(v1.w);
        }
        *(uint4*)&Bs[p][kB*BS_STRIDE + nB] =
            make_uint4(f2tf(v0.x), f2tf(v0.y), f2tf(v0.z), f2tf(v0.w));
        *(uint4*)&Bs[p][(kB+8)*BS_STRIDE + nB] =
            make_uint4(f2tf(v1.x), f2tf(v1.y), f2tf(v1.z), f2tf(v1.w));
    };
    auto COMPUTE = [&](int p){
        #pragma unroll
        for (int ks = 0; ks < 16; ks += 8){
            uint32_t a[4][4], b[4][2];
            #pragma unroll
            for (int mi = 0; mi < 4; mi++){
                int rb = wm*64 + mi*16 + gid;
                a[mi][0] = As[p][rb*AS_STRIDE     + ks+ctg];
                a[mi][1] = As[p][(rb+8)*AS_STRIDE + ks+ctg];
                a[mi][2] = As[p][rb*AS_STRIDE     + ks+ctg+4];
                a[mi][3] = As[p][(rb+8)*AS_STRIDE + ks+ctg+4];
            }
            #pragma unroll
            for (int ni = 0; ni < 4; ni++){
                int cb = wn*32 + ni*8 + gid;
                b[ni][0] = Bs[p][(ks+ctg)*BS_STRIDE   + cb];
                b[ni][1] = Bs[p][(ks+ctg+4)*BS_STRIDE + cb];
            }
            #pragma unroll
            for (int mi = 0; mi < 4; mi++)
                #pragma unroll
                for (int ni = 0; ni < 4; ni++)
                    MMA_TF32(acc[mi][ni], a[mi], b[ni]);
        }
    };

    const int nT = Kc >> 4;
    LOAD(0); STORE(0, 0);
    __syncthreads();
    for (int it = 1; it < nT; it++){
        LOAD(it*16);
        COMPUTE((it-1)&1);
        STORE(it&1, it*16);
        __syncthreads();
    }
    COMPUTE((nT-1)&1);

    // --- epilogue ---
    #pragma unroll
    for (int mi = 0; mi < 4; mi++){
        int r0 = m0 + wm*64 + mi*16 + gid;
        int r1 = r0 + 8;
        bool v0r = r0 < M, v1r = r1 < M;
        float b0 = 0.f, b1 = 0.f;
        if (BIAS){ if (v0r) b0 = bias[r0]; if (v1r) b1 = bias[r1]; }
        float s0 = 0.f, q0 = 0.f, s1 = 0.f, q1 = 0.f;
        #pragma unroll
        for (int ni = 0; ni < 4; ni++){
            int cix = n0 + wn*32 + ni*8 + 2*ctg;
            float v0 = acc[mi][ni][0], v1 = acc[mi][ni][1];
            float v2 = acc[mi][ni][2], v3 = acc[mi][ni][3];
            if (BIAS){ v0 += b0; v1 += b0; v2 += b1; v3 += b1; }
            if (OUTLK){ v0 = lk(v0); v1 = lk(v1); v2 = lk(v2); v3 = lk(v3); }
            if (v0r) *(float2*)&Om[(size_t)r0*NPIX + cix] = make_float2(v0, v1);
            if (v1r) *(float2*)&Om[(size_t)r1*NPIX + cix] = make_float2(v2, v3);
            if (STATS){
                s0 += v0+v1; q0 += v0*v0+v1*v1;
                s1 += v2+v3; q1 += v2*v2+v3*v3;
            }
        }
        if (STATS){
            s0 += __shfl_down_sync(0xffffffffu, s0, 2, 4); s0 += __shfl_down_sync(0xffffffffu, s0, 1, 4);
            q0 += __shfl_down_sync(0xffffffffu, q0, 2, 4); q0 += __shfl_down_sync(0xffffffffu, q0, 1, 4);
            s1 += __shfl_down_sync(0xffffffffu, s1, 2, 4); s1 += __shfl_down_sync(0xffffffffu, s1, 1, 4);
            q1 += __shfl_down_sync(0xffffffffu, q1, 2, 4); q1 += __shfl_down_sync(0xffffffffu, q1, 1, 4);
            if (ctg == 0){
                if (v0r){ atomicAdd(&g_stats[r0], (double)s0); atomicAdd(&g_stats[1024+r0], (double)q0); }
                if (v1r){ atomicAdd(&g_stats[r1], (double)s1); atomicAdd(&g_stats[1024+r1], (double)q1); }
            }
        }
    }
}

// ---------------- residual: A += U*scale[c]+shift[c] ----------------
__global__ void k_resid(float* __restrict__ A, const float* __restrict__ U){
    int i = blockIdx.x*blockDim.x + threadIdx.x;     // float4 index
    int c = i / (NPIX/4);
    float sc = g_ss[c], sh = g_ss[1024+c];
    float4 u = ((const float4*)U)[i];
    float4 a = ((float4*)A)[i];
    a.x += u.x*sc+sh; a.y += u.y*sc+sh; a.z += u.z*sc+sh; a.w += u.w*sc+sh;
    ((float4*)A)[i] = a;
}

// ---------------- edge kernel: one warp per edge ----------------
// NOTE: InfoIdx is int32 (JAX x64 disabled -> astype(int64) is a no-op to int32)
__global__ void k_edge(const int* __restrict__ info, const float* __restrict__ msk){
    int e = blockIdx.x*8 + (threadIdx.x >> 5);
    if (e >= EE) return;
    int lane = threadIdx.x & 31;
    const int* ip = info + (size_t)e*4;
    int src = ip[0], k1 = ip[1], dst = ip[2], k2 = ip[3];
    float s = g_sig[(size_t)k1*NPIX + src] + g_sig[(size_t)k2*NPIX + dst];
    s = fminf(5.f, fmaxf(-5.f, s));
    float a = expf(s) * msk[e];
    if (a != 0.f){
        const float* xr = g_Xrm + (size_t)src*CC;
        float* xa = g_XA + (size_t)dst*CC;
        #pragma unroll
        for (int c = lane; c < CC; c += 32)
            atomicAdd(&xa[c], xr[c]*a);
        if (lane == 0) atomicAdd(&g_Asum[dst], a);
    }
}

// ---------------- X_trans = XA/(Asum+eps), in place; accumulate bn1d stats ----------------
__global__ void k_xtrans(){
    int c = threadIdx.x;  // 256
    float s = 0.f, s2 = 0.f;
    for (int r = blockIdx.x; r < NPIX; r += gridDim.x){
        float d = g_Asum[r] + 1e-5f;
        float v = g_XA[(size_t)r*CC + c] / d;
        g_XA[(size_t)r*CC + c] = v;
        s += v; s2 += v*v;
    }
    atomicAdd(&g_stats[c],      (double)s);
    atomicAdd(&g_stats[1024+c], (double)s2);
}

// ---------------- A[c][n] += bn(X_trans)[n][c]  (transposed add) ----------------
__global__ void k_transadd(){
    __shared__ float t[32][33];
    int n0 = blockIdx.x*32, c0 = blockIdx.y*32;
    for (int i = threadIdx.y; i < 32; i += 8)
        t[i][threadIdx.x] = g_XA[(size_t)(n0+i)*CC + c0 + threadIdx.x];
    __syncthreads();
    for (int i = threadIdx.y; i < 32; i += 8){
        int c = c0 + i, n = n0 + threadIdx.x;
        g_A[(size_t)c*NPIX + n] += t[threadIdx.x][i]*g_ss[c] + g_ss[1024+c];
    }
}

// ---------------- out[n][c] = bn(T)[c][n] + A[c][n] ----------------
__global__ void k_finalout(float* __restrict__ out){
    __shared__ float t[32][33];
    int n0 = blockIdx.x*32, c0 = blockIdx.y*32;
    for (int i = threadIdx.y; i < 32; i += 8){
        int c = c0 + i, n = n0 + threadIdx.x;
        t[i][threadIdx.x] = g_T[(size_t)c*NPIX + n]*g_ss[c] + g_ss[1024+c]
                          + g_A[(size_t)c*NPIX + n];
    }
    __syncthreads();
    for (int i = threadIdx.y; i < 32; i += 8)
        out[(size_t)(n0+i)*CC + c0 + threadIdx.x] = t[threadIdx.x][i];
}

// ---------------- host ----------------
extern "C" void kernel_launch(void* const* d_in, const int* in_sizes, int n_in,
                              void* d_out, int out_size){
    const float* X      = (const float*)d_in[0];
    const int*   Info   = (const int*)d_in[1];      // int32 (see k_edge note)
    const float* msk    = (const float*)d_in[2];
    const float* ppm_w0 = (const float*)d_in[3];
    const float* ppm_g0 = (const float*)d_in[4];
    const float* ppm_b0 = (const float*)d_in[5];
    const float* ppm_w1 = (const float*)d_in[6];
    const float* ppm_g1 = (const float*)d_in[7];
    const float* ppm_b1 = (const float*)d_in[8];
    const float* f1w0   = (const float*)d_in[9];
    const float* f1g0   = (const float*)d_in[10];
    const float* f1b0   = (const float*)d_in[11];
    const float* f1w1   = (const float*)d_in[12];
    const float* f1g1   = (const float*)d_in[13];
    const float* f1b1   = (const float*)d_in[14];
    const float* dw1    = (const float*)d_in[15];
    const float* db1    = (const float*)d_in[16];
    const float* dw2    = (const float*)d_in[17];
    const float* db2    = (const float*)d_in[18];
    const float* bng    = (const float*)d_in[19];
    const float* bnb    = (const float*)d_in[20];
    const float* f2w0   = (const float*)d_in[21];
    const float* f2g0   = (const float*)d_in[22];
    const float* f2b0   = (const float*)d_in[23];
    const float* f2w1   = (const float*)d_in[24];
    const float* f2g1   = (const float*)d_in[25];
    const float* f2b1   = (const float*)d_in[26];

    float *A,*T,*U,*Hh,*Xrm,*Sig,*Asum,*XA,*Hid;
    cudaGetSymbolAddress((void**)&A,    g_A);
    cudaGetSymbolAddress((void**)&T,    g_T);
    cudaGetSymbolAddress((void**)&U,    g_U);
    cudaGetSymbolAddress((void**)&Hh,   g_h);
    cudaGetSymbolAddress((void**)&Xrm,  g_Xrm);
    cudaGetSymbolAddress((void**)&Sig,  g_sig);
    cudaGetSymbolAddress((void**)&Asum, g_Asum);
    cudaGetSymbolAddress((void**)&XA,   g_XA);
    cudaGetSymbolAddress((void**)&Hid,  g_hid);

    dim3 b32x8(32,8), b1024(32,32), b512(16,32);
    dim3 gT17(WW/64, HH/32, CC);           // (3,6,256)
    dim3 gTile(WW/32, HH/32, CC);          // (6,6,256)
    dim3 gTrans(NPIX/32, CC/32);           // (1152,8)
    dim3 gM(NPIX/128, 2);                  // (288,2)  M=256
    dim3 gMK(NPIX/128, 3);                 // (288,3)  M=289

    k_zero_stats<<<1,1024>>>();

    // img = X^T (channel-major)
    k_nc2cn<<<gTrans, b32x8>>>(X, A);

    // ppm: dw17(leaky(img)) -> bn -> 1x1(leaky(bn)) -> bn -> residual
    k_dw17<<<gT17, b512>>>(A, ppm_w0, T);
    k_bnfin<<<1,256>>>(ppm_g0, ppm_b0, 256);
    k_mma<true,true,false,false,true><<<gM,256>>>(ppm_w1, T, U, 256, 256, nullptr);
    k_bnfin<<<1,256>>>(ppm_g1, ppm_b1, 256);
    k_resid<<<CC*NPIX/4/256,256>>>(A, U);

    // ffn1: 1x1(leaky(img)) -> bn -> 1x1(leaky(bn)) -> bn -> residual
    k_mma<false,true,false,false,true><<<gM,256>>>(f1w0, A, T, 256, 256, nullptr);
    k_bnfin<<<1,256>>>(f1g0, f1b0, 256);
    k_mma<true,true,false,false,true><<<gM,256>>>(f1w1, T, U, 256, 256, nullptr);
    k_bnfin<<<1,256>>>(f1g1, f1b1, 256);
    k_resid<<<CC*NPIX/4/256,256>>>(A, U);      // A = Xn

    // Xn row-major copy for edge gather
    k_cn2nc<<<gTrans, b32x8>>>(A, Xrm);

    // dis: h = leaky(W1 @ Xn + b1); sig = W2 @ h + b2
    k_mma<false,false,true,true,false><<<gM,256>>>(dw1, A, Hh, 256, 256, db1);
    k_mma<false,false,true,false,false><<<gMK,256>>>(dw2, Hh, Sig, KK, 256, db2);

    // edge aggregation
    k_zero<<<(NPIX*CC+255)/256,256>>>(XA, NPIX*CC);
    k_zero<<<(NPIX+255)/256,256>>>(Asum, NPIX);
    k_edge<<<EE/8,256>>>(Info, msk);
    k_xtrans<<<288,256>>>();
    k_bnfin<<<1,256>>>(bng, bnb, 256);
    k_transadd<<<gTrans, b32x8>>>();           // A = Xn + bn1d(X_trans)

    // ffn2: dw3x4(leaky(img)) -> bn -> 1x1 (1024->256, leaky(bn)) -> bn; out = t + img
    k_dw3<<<gTile, b1024>>>(A, f2w0, Hid);
    k_bnfin<<<4,256>>>(f2g0, f2b0, 1024);
    k_mma<true,true,false,false,true><<<gM,256>>>(f2w1, Hid, T, 256, 1024, nullptr);
    k_bnfin<<<1,256>>>(f2g1, f2b1, 256);

    k_finalout<<<gTrans, b32x8>>>((float*)d_out);
}

// round 10
// speedup vs baseline: 2.4306x; 1.3668x over previous
#include <cuda_runtime.h>
#include <math.h>
#include <stdint.h>

#define HH 192
#define WW 192
#define NPIX (HH*WW)        // 36864
#define CC 256
#define EE 294912
#define KK 289
#define SLOPE 0.01f
#define EPSV 1e-5f

// tf32 weight buffer offsets (words)
#define OFF_PPM1 0
#define OFF_F1W0 65536
#define OFF_F1W1 131072
#define OFF_DW1  196608
#define OFF_DW2  262144          // padded to 384 rows x 256
#define OFF_F2W1 360448          // 256 x 1024
#define WT_TOTAL 622592

// ---------------- scratch (device globals; no allocation) ----------------
__device__ float g_A[CC*NPIX];        // main activation, channel-major [C][N]
__device__ float g_T[CC*NPIX];        // temp
__device__ float g_U[CC*NPIX];        // temp
__device__ float g_h[CC*NPIX];        // dis hidden
__device__ float g_Xrm[NPIX*CC];      // Xn row-major for edge gather
__device__ float g_sig[KK*NPIX];      // signal [K][N]
__device__ float g_Asum[NPIX];
__device__ float g_XA[NPIX*CC];       // row-major scatter target / X_trans
__device__ float g_hid[4*CC*NPIX];    // ffn2 hidden, 1024 channels
__device__ double g_stats[2048];      // per-channel sum (0..1023), sumsq (1024..2047)
__device__ float  g_ss[2048];         // per-channel scale (0..1023), shift (1024..2047)
__device__ uint32_t g_Wtf[WT_TOTAL];  // pre-converted tf32 weights

__device__ __forceinline__ float lk(float x){ return x >= 0.f ? x : SLOPE*x; }
__device__ __forceinline__ uint32_t f2tf(float f){
    uint32_t u; asm("cvt.rna.tf32.f32 %0, %1;" : "=r"(u) : "f"(f)); return u;
}
__device__ __forceinline__ void cpasync16(uint32_t dst, const void* src){
    asm volatile("cp.async.ca.shared.global [%0], [%1], 16;" :: "r"(dst), "l"(src));
}

// ---------------- utility kernels ----------------
__global__ void k_zero(float* __restrict__ p, int n){
    int i = blockIdx.x*blockDim.x + threadIdx.x;
    if (i < n) p[i] = 0.f;
}
__global__ void k_zero_stats(){
    int i = threadIdx.x;            // 1024 threads
    g_stats[i] = 0.0; g_stats[i+1024] = 0.0;
}

// convert all GEMM weights to tf32 bit patterns (dw2 padded to 384 rows)
__global__ void k_wconv(const float* __restrict__ p1, const float* __restrict__ p2,
                        const float* __restrict__ p3, const float* __restrict__ p4,
                        const float* __restrict__ p5, const float* __restrict__ p6){
    int i = blockIdx.x*256 + threadIdx.x;
    if (i >= WT_TOTAL) return;
    uint32_t v;
    if      (i < OFF_F1W0) v = f2tf(p1[i]);
    else if (i < OFF_F1W1) v = f2tf(p2[i-OFF_F1W0]);
    else if (i < OFF_DW1)  v = f2tf(p3[i-OFF_F1W1]);
    else if (i < OFF_DW2)  v = f2tf(p4[i-OFF_DW1]);
    else if (i < OFF_F2W1){ int j = i-OFF_DW2; v = (j < KK*CC) ? f2tf(p5[j]) : 0u; }
    else                   v = f2tf(p6[i-OFF_F2W1]);
    g_Wtf[i] = v;
}

// BN finalize: scale/shift from stats, reset stats.
__global__ void k_bnfin(const float* __restrict__ g, const float* __restrict__ b, int nch){
    int c = blockIdx.x*blockDim.x + threadIdx.x;
    if (c >= nch) return;
    double s = g_stats[c], s2 = g_stats[1024+c];
    float m   = (float)(s  / (double)NPIX);
    float var = (float)(s2 / (double)NPIX) - m*m;
    float sc  = g[c] * rsqrtf(var + EPSV);
    g_ss[c]      = sc;
    g_ss[1024+c] = b[c] - m*sc;
    g_stats[c] = 0.0; g_stats[1024+c] = 0.0;
}

// (N,C) -> (C,N)
__global__ void k_nc2cn(const float* __restrict__ in, float* __restrict__ out){
    __shared__ float t[32][33];
    int n0 = blockIdx.x*32, c0 = blockIdx.y*32;
    for (int i = threadIdx.y; i < 32; i += 8)
        t[i][threadIdx.x] = in[(size_t)(n0+i)*CC + c0 + threadIdx.x];
    __syncthreads();
    for (int i = threadIdx.y; i < 32; i += 8)
        out[(size_t)(c0+i)*NPIX + n0 + threadIdx.x] = t[threadIdx.x][i];
}
// (C,N) -> (N,C)
__global__ void k_cn2nc(const float* __restrict__ in, float* __restrict__ out){
    __shared__ float t[32][33];
    int n0 = blockIdx.x*32, c0 = blockIdx.y*32;
    for (int i = threadIdx.y; i < 32; i += 8)
        t[i][threadIdx.x] = in[(size_t)(c0+i)*NPIX + n0 + threadIdx.x];
    __syncthreads();
    for (int i = threadIdx.y; i < 32; i += 8)
        out[(size_t)(n0+i)*CC + c0 + threadIdx.x] = t[threadIdx.x][i];
}

// ---------------- depthwise 17x17, 4 outputs/thread, accumulates BN stats ----------------
__global__ void __launch_bounds__(512) k_dw17(const float* __restrict__ A,
                                              const float* __restrict__ w0,
                                              float* __restrict__ Om){
    __shared__ float sIn[48][80];
    __shared__ float sW[289];
    __shared__ float sRedS[16], sRedQ[16];
    int c  = blockIdx.z;
    int x0 = blockIdx.x*64, y0 = blockIdx.y*32;
    const float* Ac = A + (size_t)c*NPIX;
    int tx = threadIdx.x, ty = threadIdx.y;
    int tid = ty*16 + tx;
    if (tid < 289) sW[tid] = w0[c*289 + tid];
    for (int i = tid; i < 48*80; i += 512){
        int ly = i/80, lx = i%80;
        int gx = x0 - 8 + lx, gy = y0 - 8 + ly;
        float v = 0.f;
        if ((unsigned)gx < WW && (unsigned)gy < HH) v = lk(Ac[gy*WW + gx]);
        sIn[ly][lx] = v;
    }
    __syncthreads();
    float a0 = 0.f, a1 = 0.f, a2 = 0.f, a3 = 0.f;
    #pragma unroll
    for (int ky = 0; ky < 17; ky++){
        const float* rp = &sIn[ty+ky][tx*4];
        float v[20];
        #pragma unroll
        for (int q = 0; q < 5; q++) *(float4*)&v[q*4] = *(const float4*)&rp[q*4];
        #pragma unroll
        for (int kx = 0; kx < 17; kx++){
            float w = sW[ky*17+kx];
            a0 += v[kx]*w; a1 += v[kx+1]*w; a2 += v[kx+2]*w; a3 += v[kx+3]*w;
        }
    }
    int n = (y0+ty)*WW + x0 + tx*4;
    *(float4*)&Om[(size_t)c*NPIX + n] = make_float4(a0,a1,a2,a3);
    float s  = a0+a1+a2+a3;
    float s2 = a0*a0+a1*a1+a2*a2+a3*a3;
    #pragma unroll
    for (int o = 16; o > 0; o >>= 1){
        s  += __shfl_down_sync(0xffffffffu, s,  o);
        s2 += __shfl_down_sync(0xffffffffu, s2, o);
    }
    if ((tid & 31) == 0){ sRedS[tid>>5] = s; sRedQ[tid>>5] = s2; }
    __syncthreads();
    if (tid < 16){
        s = sRedS[tid]; s2 = sRedQ[tid];
        #pragma unroll
        for (int o = 8; o > 0; o >>= 1){
            s  += __shfl_down_sync(0xffffu, s,  o, 16);
            s2 += __shfl_down_sync(0xffffu, s2, o, 16);
        }
        if (tid == 0){
            atomicAdd(&g_stats[c],      (double)s);
            atomicAdd(&g_stats[1024+c], (double)s2);
        }
    }
}

// ---------------- depthwise 3x3 with channel multiplier 4, block-reduced stats ----------------
__global__ void __launch_bounds__(1024) k_dw3(const float* __restrict__ A,
                                              const float* __restrict__ w0,
                                              float* __restrict__ Om){
    __shared__ float sIn[34][34];
    __shared__ float sW[36];
    __shared__ float rS[4][32], rQ[4][32];
    int c  = blockIdx.z;
    int x0 = blockIdx.x*32, y0 = blockIdx.y*32;
    const float* Ac = A + (size_t)c*NPIX;
    int tid = threadIdx.y*32 + threadIdx.x;
    int wid = tid >> 5, lane = tid & 31;
    if (tid < 36) sW[tid] = w0[c*36 + tid];
    for (int i = tid; i < 34*34; i += 1024){
        int ly = i/34, lx = i%34;
        int gx = x0 - 1 + lx, gy = y0 - 1 + ly;
        float v = 0.f;
        if ((unsigned)gx < WW && (unsigned)gy < HH) v = lk(Ac[gy*WW + gx]);
        sIn[ly][lx] = v;
    }
    __syncthreads();
    float pix[9];
    #pragma unroll
    for (int dy = 0; dy < 3; dy++)
        #pragma unroll
        for (int dx = 0; dx < 3; dx++)
            pix[dy*3+dx] = sIn[threadIdx.y+dy][threadIdx.x+dx];
    int n = (y0+threadIdx.y)*WW + x0 + threadIdx.x;
    #pragma unroll
    for (int j = 0; j < 4; j++){
        float acc = 0.f;
        #pragma unroll
        for (int q = 0; q < 9; q++) acc += pix[q] * sW[j*9+q];
        Om[(size_t)(4*c+j)*NPIX + n] = acc;
        float s = acc, s2 = acc*acc;
        #pragma unroll
        for (int o = 16; o > 0; o >>= 1){
            s  += __shfl_down_sync(0xffffffffu, s,  o);
            s2 += __shfl_down_sync(0xffffffffu, s2, o);
        }
        if (lane == 0){ rS[j][wid] = s; rQ[j][wid] = s2; }
    }
    __syncthreads();
    if (wid < 4){
        float s = rS[wid][lane], s2 = rQ[wid][lane];
        #pragma unroll
        for (int o = 16; o > 0; o >>= 1){
            s  += __shfl_down_sync(0xffffffffu, s,  o);
            s2 += __shfl_down_sync(0xffffffffu, s2, o);
        }
        if (lane == 0){
            atomicAdd(&g_stats[4*c+wid],      (double)s);
            atomicAdd(&g_stats[1024+4*c+wid], (double)s2);
        }
    }
}

// ---------------- TF32 tensor-core GEMM, double-buffered, cp.async W path ----------------
// Out(M,N) = Wtf(M,Kc tf32) @ A(Kc,N). Block 128x128, k-step 16, 8 warps 64x32, mma m16n8k8.
// W rows are padded (no bounds check) — dw2 region padded to 384 zero rows.
#define MMA_TF32(d, a, b) asm volatile( \
  "mma.sync.aligned.m16n8k8.row.col.f32.tf32.tf32.f32 " \
  "{%0,%1,%2,%3}, {%4,%5,%6,%7}, {%8,%9}, {%0,%1,%2,%3};" \
  : "+f"(d[0]), "+f"(d[1]), "+f"(d[2]), "+f"(d[3]) \
  : "r"(a[0]), "r"(a[1]), "r"(a[2]), "r"(a[3]), "r"(b[0]), "r"(b[1]))

#define AS_STRIDE 20   // 16 + 4 pad
#define BS_STRIDE 136  // 128 + 8 pad

template<bool TRANS, bool INLK, bool BIAS, bool OUTLK, bool STATS>
__global__ void __launch_bounds__(256,2) k_mma(const uint32_t* __restrict__ Wm,
                                               const float* __restrict__ Am,
                                               float* __restrict__ Om,
                                               int M, int Kc,
                                               const float* __restrict__ bias){
    __shared__ __align__(16) uint32_t As[2][128*AS_STRIDE];
    __shared__ __align__(16) uint32_t Bs[2][16*BS_STRIDE];
    const int tid  = threadIdx.x;
    const int lane = tid & 31;
    const int wid  = tid >> 5;
    const int gid  = lane >> 2, ctg = lane & 3;
    const int wm   = wid & 1,  wn  = wid >> 1;
    const int m0 = blockIdx.y*128, n0 = blockIdx.x*128;

    const int mA  = tid >> 1;          // 0..127
    const int kqA = (tid & 1)*8;       // 0 or 8
    const int kB  = wid;               // 0..7
    const int nB  = lane*4;

    float acc[4][4][4];
    #pragma unroll
    for (int i = 0; i < 4; i++)
        #pragma unroll
        for (int j = 0; j < 4; j++)
            #pragma unroll
            for (int q = 0; q < 4; q++) acc[i][j][q] = 0.f;

    float4 ba, bb;

    auto WASYNC = [&](int p, int k0){
        const uint32_t* wp = &Wm[(size_t)(m0+mA)*Kc + k0 + kqA];
        uint32_t d0 = (uint32_t)__cvta_generic_to_shared(&As[p][mA*AS_STRIDE + kqA]);
        cpasync16(d0, wp);
        cpasync16(d0 + 16, wp + 4);
    };
    auto LOADB = [&](int k0){
        ba = *(const float4*)&Am[(size_t)(k0+kB)*NPIX   + n0 + nB];
        bb = *(const float4*)&Am[(size_t)(k0+kB+8)*NPIX + n0 + nB];
    };
    auto STOREB = [&](int p, int k0){
        float4 v0 = ba, v1 = bb;
        if (TRANS){
            float sc0 = g_ss[k0+kB],   sh0 = g_ss[1024+k0+kB];
            float sc1 = g_ss[k0+kB+8], sh1 = g_ss[1024+k0+kB+8];
            v0.x = v0.x*sc0+sh0; v0.y = v0.y*sc0+sh0; v0.z = v0.z*sc0+sh0; v0.w = v0.w*sc0+sh0;
            v1.x = v1.x*sc1+sh1; v1.y = v1.y*sc1+sh1; v1.z = v1.z*sc1+sh1; v1.w = v1.w*sc1+sh1;
        }
        if (INLK){
            v0.x = lk(v0.x); v0.y = lk(v0.y); v0.z = lk(v0.z); v0.w = lk(v0.w);
            v1.x = lk(v1.x); v1.y = lk(v1.y); v1.z = lk(v1.z); v1.w = lk(v1.w);
        }
        *(uint4*)&Bs[p][kB*BS_STRIDE + nB] =
            make_uint4(f2tf(v0.x), f2tf(v0.y), f2tf(v0.z), f2tf(v0.w));
        *(uint4*)&Bs[p][(kB+8)*BS_STRIDE + nB] =
            make_uint4(f2tf(v1.x), f2tf(v1.y), f2tf(v1.z), f2tf(v1.w));
    };
    auto COMPUTE = [&](int p){
        #pragma unroll
        for (int ks = 0; ks < 16; ks += 8){
            uint32_t a[4][4], b[4][2];
            #pragma unroll
            for (int mi = 0; mi < 4; mi++){
                int rb = wm*64 + mi*16 + gid;
                a[mi][0] = As[p][rb*AS_STRIDE     + ks+ctg];
                a[mi][1] = As[p][(rb+8)*AS_STRIDE + ks+ctg];
                a[mi][2] = As[p][rb*AS_STRIDE     + ks+ctg+4];
                a[mi][3] = As[p][(rb+8)*AS_STRIDE + ks+ctg+4];
            }
            #pragma unroll
            for (int ni = 0; ni < 4; ni++){
                int cb = wn*32 + ni*8 + gid;
                b[ni][0] = Bs[p][(ks+ctg)*BS_STRIDE   + cb];
                b[ni][1] = Bs[p][(ks+ctg+4)*BS_STRIDE + cb];
            }
            #pragma unroll
            for (int mi = 0; mi < 4; mi++)
                #pragma unroll
                for (int ni = 0; ni < 4; ni++)
                    MMA_TF32(acc[mi][ni], a[mi], b[ni]);
        }
    };

    const int nT = Kc >> 4;
    WASYNC(0, 0);
    asm volatile("cp.async.commit_group;");
    LOADB(0);
    STOREB(0, 0);
    asm volatile("cp.async.wait_group 0;" ::: "memory");
    __syncthreads();
    for (int it = 1; it < nT; it++){
        WASYNC(it&1, it*16);
        asm volatile("cp.async.commit_group;");
        LOADB(it*16);
        COMPUTE((it-1)&1);
        STOREB(it&1, it*16);
        asm volatile("cp.async.wait_group 0;" ::: "memory");
        __syncthreads();
    }
    COMPUTE((nT-1)&1);

    // --- epilogue ---
    #pragma unroll
    for (int mi = 0; mi < 4; mi++){
        int r0 = m0 + wm*64 + mi*16 + gid;
        int r1 = r0 + 8;
        bool v0r = r0 < M, v1r = r1 < M;
        float b0 = 0.f, b1 = 0.f;
        if (BIAS){ if (v0r) b0 = bias[r0]; if (v1r) b1 = bias[r1]; }
        float s0 = 0.f, q0 = 0.f, s1 = 0.f, q1 = 0.f;
        #pragma unroll
        for (int ni = 0; ni < 4; ni++){
            int cix = n0 + wn*32 + ni*8 + 2*ctg;
            float v0 = acc[mi][ni][0], v1 = acc[mi][ni][1];
            float v2 = acc[mi][ni][2], v3 = acc[mi][ni][3];
            if (BIAS){ v0 += b0; v1 += b0; v2 += b1; v3 += b1; }
            if (OUTLK){ v0 = lk(v0); v1 = lk(v1); v2 = lk(v2); v3 = lk(v3); }
            if (v0r) *(float2*)&Om[(size_t)r0*NPIX + cix] = make_float2(v0, v1);
            if (v1r) *(float2*)&Om[(size_t)r1*NPIX + cix] = make_float2(v2, v3);
            if (STATS){
                s0 += v0+v1; q0 += v0*v0+v1*v1;
                s1 += v2+v3; q1 += v2*v2+v3*v3;
            }
        }
        if (STATS){
            s0 += __shfl_down_sync(0xffffffffu, s0, 2, 4); s0 += __shfl_down_sync(0xffffffffu, s0, 1, 4);
            q0 += __shfl_down_sync(0xffffffffu, q0, 2, 4); q0 += __shfl_down_sync(0xffffffffu, q0, 1, 4);
            s1 += __shfl_down_sync(0xffffffffu, s1, 2, 4); s1 += __shfl_down_sync(0xffffffffu, s1, 1, 4);
            q1 += __shfl_down_sync(0xffffffffu, q1, 2, 4); q1 += __shfl_down_sync(0xffffffffu, q1, 1, 4);
            if (ctg == 0){
                if (v0r){ atomicAdd(&g_stats[r0], (double)s0); atomicAdd(&g_stats[1024+r0], (double)q0); }
                if (v1r){ atomicAdd(&g_stats[r1], (double)s1); atomicAdd(&g_stats[1024+r1], (double)q1); }
            }
        }
    }
}

// ---------------- residual: A += U*scale[c]+shift[c] ----------------
__global__ void k_resid(float* __restrict__ A, const float* __restrict__ U){
    int i = blockIdx.x*blockDim.x + threadIdx.x;     // float4 index
    int c = i / (NPIX/4);
    float sc = g_ss[c], sh = g_ss[1024+c];
    float4 u = ((const float4*)U)[i];
    float4 a = ((float4*)A)[i];
    a.x += u.x*sc+sh; a.y += u.y*sc+sh; a.z += u.z*sc+sh; a.w += u.w*sc+sh;
    ((float4*)A)[i] = a;
}

// ---------------- edge kernel: one warp per edge ----------------
// NOTE: InfoIdx is int32 (JAX x64 disabled -> astype(int64) is a no-op to int32)
__global__ void k_edge(const int* __restrict__ info, const float* __restrict__ msk){
    int e = blockIdx.x*8 + (threadIdx.x >> 5);
    if (e >= EE) return;
    int lane = threadIdx.x & 31;
    int4 ii = *(const int4*)(info + (size_t)e*4);
    int src = ii.x, k1 = ii.y, dst = ii.z, k2 = ii.w;
    float s = g_sig[(size_t)k1*NPIX + src] + g_sig[(size_t)k2*NPIX + dst];
    s = fminf(5.f, fmaxf(-5.f, s));
    float a = expf(s) * msk[e];
    if (a != 0.f){
        const float* xr = g_Xrm + (size_t)src*CC;
        float* xa = g_XA + (size_t)dst*CC;
        #pragma unroll
        for (int c = lane; c < CC; c += 32)
            atomicAdd(&xa[c], xr[c]*a);
        if (lane == 0) atomicAdd(&g_Asum[dst], a);
    }
}

// ---------------- X_trans = XA/(Asum+eps), in place; accumulate bn1d stats ----------------
__global__ void k_xtrans(){
    int c = threadIdx.x;  // 256
    float s = 0.f, s2 = 0.f;
    for (int r = blockIdx.x; r < NPIX; r += gridDim.x){
        float d = g_Asum[r] + 1e-5f;
        float v = g_XA[(size_t)r*CC + c] / d;
        g_XA[(size_t)r*CC + c] = v;
        s += v; s2 += v*v;
    }
    atomicAdd(&g_stats[c],      (double)s);
    atomicAdd(&g_stats[1024+c], (double)s2);
}

// ---------------- A[c][n] += bn(X_trans)[n][c]  (transposed add) ----------------
__global__ void k_transadd(){
    __shared__ float t[32][33];
    int n0 = blockIdx.x*32, c0 = blockIdx.y*32;
    for (int i = threadIdx.y; i < 32; i += 8)
        t[i][threadIdx.x] = g_XA[(size_t)(n0+i)*CC + c0 + threadIdx.x];
    __syncthreads();
    for (int i = threadIdx.y; i < 32; i += 8){
        int c = c0 + i, n = n0 + threadIdx.x;
        g_A[(size_t)c*NPIX + n] += t[threadIdx.x][i]*g_ss[c] + g_ss[1024+c];
    }
}

// ---------------- out[n][c] = bn(T)[c][n] + A[c][n] ----------------
__global__ void k_finalout(float* __restrict__ out){
    __shared__ float t[32][33];
    int n0 = blockIdx.x*32, c0 = blockIdx.y*32;
    for (int i = threadIdx.y; i < 32; i += 8){
        int c = c0 + i, n = n0 + threadIdx.x;
        t[i][threadIdx.x] = g_T[(size_t)c*NPIX + n]*g_ss[c] + g_ss[1024+c]
                          + g_A[(size_t)c*NPIX + n];
    }
    __syncthreads();
    for (int i = threadIdx.y; i < 32; i += 8)
        out[(size_t)(n0+i)*CC + c0 + threadIdx.x] = t[threadIdx.x][i];
}

// ---------------- host ----------------
extern "C" void kernel_launch(void* const* d_in, const int* in_sizes, int n_in,
                              void* d_out, int out_size){
    const float* X      = (const float*)d_in[0];
    const int*   Info   = (const int*)d_in[1];      // int32 (see k_edge note)
    const float* msk    = (const float*)d_in[2];
    const float* ppm_w0 = (const float*)d_in[3];
    const float* ppm_g0 = (const float*)d_in[4];
    const float* ppm_b0 = (const float*)d_in[5];
    const float* ppm_w1 = (const float*)d_in[6];
    const float* ppm_g1 = (const float*)d_in[7];
    const float* ppm_b1 = (const float*)d_in[8];
    const float* f1w0   = (const float*)d_in[9];
    const float* f1g0   = (const float*)d_in[10];
    const float* f1b0   = (const float*)d_in[11];
    const float* f1w1   = (const float*)d_in[12];
    const float* f1g1   = (const float*)d_in[13];
    const float* f1b1   = (const float*)d_in[14];
    const float* dw1    = (const float*)d_in[15];
    const float* db1    = (const float*)d_in[16];
    const float* dw2    = (const float*)d_in[17];
    const float* db2    = (const float*)d_in[18];
    const float* bng    = (const float*)d_in[19];
    const float* bnb    = (const float*)d_in[20];
    const float* f2w0   = (const float*)d_in[21];
    const float* f2g0   = (const float*)d_in[22];
    const float* f2b0   = (const float*)d_in[23];
    const float* f2w1   = (const float*)d_in[24];
    const float* f2g1   = (const float*)d_in[25];
    const float* f2b1   = (const float*)d_in[26];

    float *A,*T,*U,*Hh,*Xrm,*Sig,*Asum,*XA,*Hid;
    uint32_t *Wtf;
    cudaGetSymbolAddress((void**)&A,    g_A);
    cudaGetSymbolAddress((void**)&T,    g_T);
    cudaGetSymbolAddress((void**)&U,    g_U);
    cudaGetSymbolAddress((void**)&Hh,   g_h);
    cudaGetSymbolAddress((void**)&Xrm,  g_Xrm);
    cudaGetSymbolAddress((void**)&Sig,  g_sig);
    cudaGetSymbolAddress((void**)&Asum, g_Asum);
    cudaGetSymbolAddress((void**)&XA,   g_XA);
    cudaGetSymbolAddress((void**)&Hid,  g_hid);
    cudaGetSymbolAddress((void**)&Wtf,  g_Wtf);

    dim3 b32x8(32,8), b1024(32,32), b512(16,32);
    dim3 gT17(WW/64, HH/32, CC);           // (3,6,256)
    dim3 gTile(WW/32, HH/32, CC);          // (6,6,256)
    dim3 gTrans(NPIX/32, CC/32);           // (1152,8)
    dim3 gM(NPIX/128, 2);                  // (288,2)  M=256
    dim3 gMK(NPIX/128, 3);                 // (288,3)  M=289 (padded W rows to 384)

    // launch order matters for ncu (-s 5 -c 1): index 5 must be the first k_mma
    k_zero_stats<<<1,1024>>>();                                    // 0
    k_wconv<<<(WT_TOTAL+255)/256,256>>>(ppm_w1, f1w0, f1w1, dw1, dw2, f2w1); // 1
    k_nc2cn<<<gTrans, b32x8>>>(X, A);                              // 2
    k_dw17<<<gT17, b512>>>(A, ppm_w0, T);                          // 3
    k_bnfin<<<1,256>>>(ppm_g0, ppm_b0, 256);                       // 4
    k_mma<true,true,false,false,true><<<gM,256>>>(Wtf+OFF_PPM1, T, U, 256, 256, nullptr); // 5 <- profiled
    k_bnfin<<<1,256>>>(ppm_g1, ppm_b1, 256);
    k_resid<<<CC*NPIX/4/256,256>>>(A, U);

    // ffn1
    k_mma<false,true,false,false,true><<<gM,256>>>(Wtf+OFF_F1W0, A, T, 256, 256, nullptr);
    k_bnfin<<<1,256>>>(f1g0, f1b0, 256);
    k_mma<true,true,false,false,true><<<gM,256>>>(Wtf+OFF_F1W1, T, U, 256, 256, nullptr);
    k_bnfin<<<1,256>>>(f1g1, f1b1, 256);
    k_resid<<<CC*NPIX/4/256,256>>>(A, U);      // A = Xn

    // Xn row-major copy for edge gather
    k_cn2nc<<<gTrans, b32x8>>>(A, Xrm);

    // dis: h = leaky(W1 @ Xn + b1); sig = W2 @ h + b2
    k_mma<false,false,true,true,false><<<gM,256>>>(Wtf+OFF_DW1, A, Hh, 256, 256, db1);
    k_mma<false,false,true,false,false><<<gMK,256>>>(Wtf+OFF_DW2, Hh, Sig, KK, 256, db2);

    // edge aggregation
    k_zero<<<(NPIX*CC+255)/256,256>>>(XA, NPIX*CC);
    k_zero<<<(NPIX+255)/256,256>>>(Asum, NPIX);
    k_edge<<<EE/8,256>>>(Info, msk);
    k_xtrans<<<288,256>>>();
    k_bnfin<<<1,256>>>(bng, bnb, 256);
    k_transadd<<<gTrans, b32x8>>>();           // A = Xn + bn1d(X_trans)

    // ffn2
    k_dw3<<<gTile, b1024>>>(A, f2w0, Hid);
    k_bnfin<<<4,256>>>(f2g0, f2b0, 1024);
    k_mma<true,true,false,false,true><<<gM,256>>>(Wtf+OFF_F2W1, Hid, T, 256, 1024, nullptr);
    k_bnfin<<<1,256>>>(f2g1, f2b1, 256);

    k_finalout<<<gTrans, b32x8>>>((float*)d_out);
}

// round 12
// speedup vs baseline: 2.5221x; 1.0376x over previous
#include <cuda_runtime.h>
#include <math.h>
#include <stdint.h>

#define HH 192
#define WW 192
#define NPIX (HH*WW)        // 36864
#define CC 256
#define EE 294912
#define KK 289
#define SLOPE 0.01f
#define EPSV 1e-5f

// tf32 weight buffer offsets (words)
#define OFF_PPM1 0
#define OFF_F1W0 65536
#define OFF_F1W1 131072
#define OFF_DW1  196608
#define OFF_DW2  262144          // padded to 384 rows x 256
#define OFF_F2W1 360448          // 256 x 1024
#define WT_TOTAL 622592

// ---------------- scratch (device globals; no allocation) ----------------
__device__ float g_A[CC*NPIX];        // main activation, channel-major [C][N]
__device__ float g_T[CC*NPIX];        // temp
__device__ float g_U[CC*NPIX];        // temp
__device__ float g_h[CC*NPIX];        // dis hidden
__device__ float g_Xrm[NPIX*CC];      // Xn row-major for edge gather
__device__ float g_sig[KK*NPIX];      // signal [K][N]
__device__ float g_Asum[NPIX];
__device__ float g_XA[NPIX*CC];       // row-major scatter target / X_trans
__device__ float g_hid[4*CC*NPIX];    // ffn2 hidden, 1024 channels
__device__ double g_stats[2048];      // per-channel sum (0..1023), sumsq (1024..2047)
__device__ float  g_ss[2048];         // per-channel scale (0..1023), shift (1024..2047)
__device__ uint32_t g_Wtf[WT_TOTAL];  // pre-converted tf32 weights

__device__ __forceinline__ float lk(float x){ return x >= 0.f ? x : SLOPE*x; }
__device__ __forceinline__ uint32_t f2tf(float f){
    uint32_t u; asm("cvt.rna.tf32.f32 %0, %1;" : "=r"(u) : "f"(f)); return u;
}
__device__ __forceinline__ void cpasync16(uint32_t dst, const void* src){
    asm volatile("cp.async.ca.shared.global [%0], [%1], 16;" :: "r"(dst), "l"(src));
}
__device__ __forceinline__ void red4(float* p, float a, float b, float c, float d){
    asm volatile("red.global.add.v4.f32 [%0], {%1,%2,%3,%4};"
                 :: "l"(p), "f"(a), "f"(b), "f"(c), "f"(d) : "memory");
}

// ---------------- utility kernels ----------------
__global__ void k_zero(float* __restrict__ p, int n){
    int i = blockIdx.x*blockDim.x + threadIdx.x;
    if (i < n) p[i] = 0.f;
}
__global__ void k_zero_stats(){
    int i = threadIdx.x;            // 1024 threads
    g_stats[i] = 0.0; g_stats[i+1024] = 0.0;
}

// convert all GEMM weights to tf32 bit patterns (dw2 padded to 384 rows)
__global__ void k_wconv(const float* __restrict__ p1, const float* __restrict__ p2,
                        const float* __restrict__ p3, const float* __restrict__ p4,
                        const float* __restrict__ p5, const float* __restrict__ p6){
    int i = blockIdx.x*256 + threadIdx.x;
    if (i >= WT_TOTAL) return;
    uint32_t v;
    if      (i < OFF_F1W0) v = f2tf(p1[i]);
    else if (i < OFF_F1W1) v = f2tf(p2[i-OFF_F1W0]);
    else if (i < OFF_DW1)  v = f2tf(p3[i-OFF_F1W1]);
    else if (i < OFF_DW2)  v = f2tf(p4[i-OFF_DW1]);
    else if (i < OFF_F2W1){ int j = i-OFF_DW2; v = (j < KK*CC) ? f2tf(p5[j]) : 0u; }
    else                   v = f2tf(p6[i-OFF_F2W1]);
    g_Wtf[i] = v;
}

// BN finalize: scale/shift from stats, reset stats.
__global__ void k_bnfin(const float* __restrict__ g, const float* __restrict__ b, int nch){
    int c = blockIdx.x*blockDim.x + threadIdx.x;
    if (c >= nch) return;
    double s = g_stats[c], s2 = g_stats[1024+c];
    float m   = (float)(s  / (double)NPIX);
    float var = (float)(s2 / (double)NPIX) - m*m;
    float sc  = g[c] * rsqrtf(var + EPSV);
    g_ss[c]      = sc;
    g_ss[1024+c] = b[c] - m*sc;
    g_stats[c] = 0.0; g_stats[1024+c] = 0.0;
}

// (N,C) -> (C,N)
__global__ void k_nc2cn(const float* __restrict__ in, float* __restrict__ out){
    __shared__ float t[32][33];
    int n0 = blockIdx.x*32, c0 = blockIdx.y*32;
    for (int i = threadIdx.y; i < 32; i += 8)
        t[i][threadIdx.x] = in[(size_t)(n0+i)*CC + c0 + threadIdx.x];
    __syncthreads();
    for (int i = threadIdx.y; i < 32; i += 8)
        out[(size_t)(c0+i)*NPIX + n0 + threadIdx.x] = t[threadIdx.x][i];
}
// (C,N) -> (N,C)
__global__ void k_cn2nc(const float* __restrict__ in, float* __restrict__ out){
    __shared__ float t[32][33];
    int n0 = blockIdx.x*32, c0 = blockIdx.y*32;
    for (int i = threadIdx.y; i < 32; i += 8)
        t[i][threadIdx.x] = in[(size_t)(c0+i)*NPIX + n0 + threadIdx.x];
    __syncthreads();
    for (int i = threadIdx.y; i < 32; i += 8)
        out[(size_t)(n0+i)*CC + c0 + threadIdx.x] = t[threadIdx.x][i];
}

// ---------------- depthwise 17x17, 8 outputs/thread (two 4-wide segments) ----------------
// block (8,32)=256; output tile 64(x) x 32(y); thread -> x = tx*4+{0..3} and tx*4+32+{0..3}
__global__ void __launch_bounds__(256) k_dw17(const float* __restrict__ A,
                                              const float* __restrict__ w0,
                                              float* __restrict__ Om){
    __shared__ float sIn[48][80];
    __shared__ float sW[289];
    __shared__ float sRedS[8], sRedQ[8];
    int c  = blockIdx.z;
    int x0 = blockIdx.x*64, y0 = blockIdx.y*32;
    const float* Ac = A + (size_t)c*NPIX;
    int tx = threadIdx.x, ty = threadIdx.y;
    int tid = ty*8 + tx;
    for (int i = tid; i < 289; i += 256) sW[i] = w0[c*289 + i];
    for (int i = tid; i < 48*80; i += 256){
        int ly = i/80, lx = i%80;
        int gx = x0 - 8 + lx, gy = y0 - 8 + ly;
        float v = 0.f;
        if ((unsigned)gx < WW && (unsigned)gy < HH) v = lk(Ac[gy*WW + gx]);
        sIn[ly][lx] = v;
    }
    __syncthreads();
    float a0=0.f,a1=0.f,a2=0.f,a3=0.f,a4=0.f,a5=0.f,a6=0.f,a7=0.f;
    #pragma unroll
    for (int ky = 0; ky < 17; ky++){
        const float* rp = &sIn[ty+ky][tx*4];
        float u[20], v[20];
        #pragma unroll
        for (int q = 0; q < 5; q++) *(float4*)&u[q*4] = *(const float4*)&rp[q*4];
        #pragma unroll
        for (int q = 0; q < 5; q++) *(float4*)&v[q*4] = *(const float4*)&rp[32+q*4];
        #pragma unroll
        for (int kx = 0; kx < 17; kx++){
            float w = sW[ky*17+kx];
            a0 += u[kx]*w; a1 += u[kx+1]*w; a2 += u[kx+2]*w; a3 += u[kx+3]*w;
            a4 += v[kx]*w; a5 += v[kx+1]*w; a6 += v[kx+2]*w; a7 += v[kx+3]*w;
        }
    }
    int n = (y0+ty)*WW + x0 + tx*4;
    *(float4*)&Om[(size_t)c*NPIX + n]      = make_float4(a0,a1,a2,a3);
    *(float4*)&Om[(size_t)c*NPIX + n + 32] = make_float4(a4,a5,a6,a7);
    float s  = a0+a1+a2+a3+a4+a5+a6+a7;
    float s2 = a0*a0+a1*a1+a2*a2+a3*a3+a4*a4+a5*a5+a6*a6+a7*a7;
    #pragma unroll
    for (int o = 16; o > 0; o >>= 1){
        s  += __shfl_down_sync(0xffffffffu, s,  o);
        s2 += __shfl_down_sync(0xffffffffu, s2, o);
    }
    if ((tid & 31) == 0){ sRedS[tid>>5] = s; sRedQ[tid>>5] = s2; }
    __syncthreads();
    if (tid < 8){
        s = sRedS[tid]; s2 = sRedQ[tid];
        #pragma unroll
        for (int o = 4; o > 0; o >>= 1){
            s  += __shfl_down_sync(0xffu, s,  o, 8);
            s2 += __shfl_down_sync(0xffu, s2, o, 8);
        }
        if (tid == 0){
            atomicAdd(&g_stats[c],      (double)s);
            atomicAdd(&g_stats[1024+c], (double)s2);
        }
    }
}

// ---------------- depthwise 3x3 with channel multiplier 4, block-reduced stats ----------------
__global__ void __launch_bounds__(1024) k_dw3(const float* __restrict__ A,
                                              const float* __restrict__ w0,
                                              float* __restrict__ Om){
    __shared__ float sIn[34][34];
    __shared__ float sW[36];
    __shared__ float rS[4][32], rQ[4][32];
    int c  = blockIdx.z;
    int x0 = blockIdx.x*32, y0 = blockIdx.y*32;
    const float* Ac = A + (size_t)c*NPIX;
    int tid = threadIdx.y*32 + threadIdx.x;
    int wid = tid >> 5, lane = tid & 31;
    if (tid < 36) sW[tid] = w0[c*36 + tid];
    for (int i = tid; i < 34*34; i += 1024){
        int ly = i/34, lx = i%34;
        int gx = x0 - 1 + lx, gy = y0 - 1 + ly;
        float v = 0.f;
        if ((unsigned)gx < WW && (unsigned)gy < HH) v = lk(Ac[gy*WW + gx]);
        sIn[ly][lx] = v;
    }
    __syncthreads();
    float pix[9];
    #pragma unroll
    for (int dy = 0; dy < 3; dy++)
        #pragma unroll
        for (int dx = 0; dx < 3; dx++)
            pix[dy*3+dx] = sIn[threadIdx.y+dy][threadIdx.x+dx];
    int n = (y0+threadIdx.y)*WW + x0 + threadIdx.x;
    #pragma unroll
    for (int j = 0; j < 4; j++){
        float acc = 0.f;
        #pragma unroll
        for (int q = 0; q < 9; q++) acc += pix[q] * sW[j*9+q];
        Om[(size_t)(4*c+j)*NPIX + n] = acc;
        float s = acc, s2 = acc*acc;
        #pragma unroll
        for (int o = 16; o > 0; o >>= 1){
            s  += __shfl_down_sync(0xffffffffu, s,  o);
            s2 += __shfl_down_sync(0xffffffffu, s2, o);
        }
        if (lane == 0){ rS[j][wid] = s; rQ[j][wid] = s2; }
    }
    __syncthreads();
    if (wid < 4){
        float s = rS[wid][lane], s2 = rQ[wid][lane];
        #pragma unroll
        for (int o = 16; o > 0; o >>= 1){
            s  += __shfl_down_sync(0xffffffffu, s,  o);
            s2 += __shfl_down_sync(0xffffffffu, s2, o);
        }
        if (lane == 0){
            atomicAdd(&g_stats[4*c+wid],      (double)s);
            atomicAdd(&g_stats[1024+4*c+wid], (double)s2);
        }
    }
}

// ---------------- TF32 tensor-core GEMM, double-buffered, cp.async W path ----------------
#define MMA_TF32(d, a, b) asm volatile( \
  "mma.sync.aligned.m16n8k8.row.col.f32.tf32.tf32.f32 " \
  "{%0,%1,%2,%3}, {%4,%5,%6,%7}, {%8,%9}, {%0,%1,%2,%3};" \
  : "+f"(d[0]), "+f"(d[1]), "+f"(d[2]), "+f"(d[3]) \
  : "r"(a[0]), "r"(a[1]), "r"(a[2]), "r"(a[3]), "r"(b[0]), "r"(b[1]))

#define AS_STRIDE 20   // 16 + 4 pad
#define BS_STRIDE 136  // 128 + 8 pad

template<bool TRANS, bool INLK, bool BIAS, bool OUTLK, bool STATS>
__global__ void __launch_bounds__(256,2) k_mma(const uint32_t* __restrict__ Wm,
                                               const float* __restrict__ Am,
                                               float* __restrict__ Om,
                                               int M, int Kc,
                                               const float* __restrict__ bias){
    __shared__ __align__(16) uint32_t As[2][128*AS_STRIDE];
    __shared__ __align__(16) uint32_t Bs[2][16*BS_STRIDE];
    const int tid  = threadIdx.x;
    const int lane = tid & 31;
    const int wid  = tid >> 5;
    const int gid  = lane >> 2, ctg = lane & 3;
    const int wm   = wid & 1,  wn  = wid >> 1;
    const int m0 = blockIdx.y*128, n0 = blockIdx.x*128;

    const int mA  = tid >> 1;          // 0..127
    const int kqA = (tid & 1)*8;       // 0 or 8
    const int kB  = wid;               // 0..7
    const int nB  = lane*4;

    float acc[4][4][4];
    #pragma unroll
    for (int i = 0; i < 4; i++)
        #pragma unroll
        for (int j = 0; j < 4; j++)
            #pragma unroll
            for (int q = 0; q < 4; q++) acc[i][j][q] = 0.f;

    float4 ba, bb;

    auto WASYNC = [&](int p, int k0){
        const uint32_t* wp = &Wm[(size_t)(m0+mA)*Kc + k0 + kqA];
        uint32_t d0 = (uint32_t)__cvta_generic_to_shared(&As[p][mA*AS_STRIDE + kqA]);
        cpasync16(d0, wp);
        cpasync16(d0 + 16, wp + 4);
    };
    auto LOADB = [&](int k0){
        ba = *(const float4*)&Am[(size_t)(k0+kB)*NPIX   + n0 + nB];
        bb = *(const float4*)&Am[(size_t)(k0+kB+8)*NPIX + n0 + nB];
    };
    auto STOREB = [&](int p, int k0){
        float4 v0 = ba, v1 = bb;
        if (TRANS){
            float sc0 = g_ss[k0+kB],   sh0 = g_ss[1024+k0+kB];
            float sc1 = g_ss[k0+kB+8], sh1 = g_ss[1024+k0+kB+8];
            v0.x = v0.x*sc0+sh0; v0.y = v0.y*sc0+sh0; v0.z = v0.z*sc0+sh0; v0.w = v0.w*sc0+sh0;
            v1.x = v1.x*sc1+sh1; v1.y = v1.y*sc1+sh1; v1.z = v1.z*sc1+sh1; v1.w = v1.w*sc1+sh1;
        }
        if (INLK){
            v0.x = lk(v0.x); v0.y = lk(v0.y); v0.z = lk(v0.z); v0.w = lk(v0.w);
            v1.x = lk(v1.x); v1.y = lk(v1.y); v1.z = lk(v1.z); v1.w = lk(v1.w);
        }
        *(uint4*)&Bs[p][kB*BS_STRIDE + nB] =
            make_uint4(f2tf(v0.x), f2tf(v0.y), f2tf(v0.z), f2tf(v0.w));
        *(uint4*)&Bs[p][(kB+8)*BS_STRIDE + nB] =
            make_uint4(f2tf(v1.x), f2tf(v1.y), f2tf(v1.z), f2tf(v1.w));
    };
    auto COMPUTE = [&](int p){
        #pragma unroll
        for (int ks = 0; ks < 16; ks += 8){
            uint32_t a[4][4], b[4][2];
            #pragma unroll
            for (int mi = 0; mi < 4; mi++){
                int rb = wm*64 + mi*16 + gid;
                a[mi][0] = As[p][rb*AS_STRIDE     + ks+ctg];
                a[mi][1] = As[p][(rb+8)*AS_STRIDE + ks+ctg];
                a[mi][2] = As[p][rb*AS_STRIDE     + ks+ctg+4];
                a[mi][3] = As[p][(rb+8)*AS_STRIDE + ks+ctg+4];
            }
            #pragma unroll
            for (int ni = 0; ni < 4; ni++){
                int cb = wn*32 + ni*8 + gid;
                b[ni][0] = Bs[p][(ks+ctg)*BS_STRIDE   + cb];
                b[ni][1] = Bs[p][(ks+ctg+4)*BS_STRIDE + cb];
            }
            #pragma unroll
            for (int mi = 0; mi < 4; mi++)
                #pragma unroll
                for (int ni = 0; ni < 4; ni++)
                    MMA_TF32(acc[mi][ni], a[mi], b[ni]);
        }
    };

    const int nT = Kc >> 4;
    WASYNC(0, 0);
    asm volatile("cp.async.commit_group;");
    LOADB(0);
    STOREB(0, 0);
    asm volatile("cp.async.wait_group 0;" ::: "memory");
    __syncthreads();
    for (int it = 1; it < nT; it++){
        WASYNC(it&1, it*16);
        asm volatile("cp.async.commit_group;");
        LOADB(it*16);
        COMPUTE((it-1)&1);
        STOREB(it&1, it*16);
        asm volatile("cp.async.wait_group 0;" ::: "memory");
        __syncthreads();
    }
    COMPUTE((nT-1)&1);

    // --- epilogue ---
    #pragma unroll
    for (int mi = 0; mi < 4; mi++){
        int r0 = m0 + wm*64 + mi*16 + gid;
        int r1 = r0 + 8;
        bool v0r = r0 < M, v1r = r1 < M;
        float b0 = 0.f, b1 = 0.f;
        if (BIAS){ if (v0r) b0 = bias[r0]; if (v1r) b1 = bias[r1]; }
        float s0 = 0.f, q0 = 0.f, s1 = 0.f, q1 = 0.f;
        #pragma unroll
        for (int ni = 0; ni < 4; ni++){
            int cix = n0 + wn*32 + ni*8 + 2*ctg;
            float v0 = acc[mi][ni][0], v1 = acc[mi][ni][1];
            float v2 = acc[mi][ni][2], v3 = acc[mi][ni][3];
            if (BIAS){ v0 += b0; v1 += b0; v2 += b1; v3 += b1; }
            if (OUTLK){ v0 = lk(v0); v1 = lk(v1); v2 = lk(v2); v3 = lk(v3); }
            if (v0r) *(float2*)&Om[(size_t)r0*NPIX + cix] = make_float2(v0, v1);
            if (v1r) *(float2*)&Om[(size_t)r1*NPIX + cix] = make_float2(v2, v3);
            if (STATS){
                s0 += v0+v1; q0 += v0*v0+v1*v1;
                s1 += v2+v3; q1 += v2*v2+v3*v3;
            }
        }
        if (STATS){
            s0 += __shfl_down_sync(0xffffffffu, s0, 2, 4); s0 += __shfl_down_sync(0xffffffffu, s0, 1, 4);
            q0 += __shfl_down_sync(0xffffffffu, q0, 2, 4); q0 += __shfl_down_sync(0xffffffffu, q0, 1, 4);
            s1 += __shfl_down_sync(0xffffffffu, s1, 2, 4); s1 += __shfl_down_sync(0xffffffffu, s1, 1, 4);
            q1 += __shfl_down_sync(0xffffffffu, q1, 2, 4); q1 += __shfl_down_sync(0xffffffffu, q1, 1, 4);
            if (ctg == 0){
                if (v0r){ atomicAdd(&g_stats[r0], (double)s0); atomicAdd(&g_stats[1024+r0], (double)q0); }
                if (v1r){ atomicAdd(&g_stats[r1], (double)s1); atomicAdd(&g_stats[1024+r1], (double)q1); }
            }
        }
    }
}

// ---------------- residual: A += U*scale[c]+shift[c] ----------------
__global__ void k_resid(float* __restrict__ A, const float* __restrict__ U){
    int i = blockIdx.x*blockDim.x + threadIdx.x;     // float4 index
    int c = i / (NPIX/4);
    float sc = g_ss[c], sh = g_ss[1024+c];
    float4 u = ((const float4*)U)[i];
    float4 a = ((float4*)A)[i];
    a.x += u.x*sc+sh; a.y += u.y*sc+sh; a.z += u.z*sc+sh; a.w += u.w*sc+sh;
    ((float4*)A)[i] = a;
}

// ---------------- edge kernel: one warp per edge, vector red.v4 scatter ----------------
// NOTE: InfoIdx is int32 (JAX x64 disabled -> astype(int64) is a no-op to int32)
__global__ void k_edge(const int* __restrict__ info, const float* __restrict__ msk){
    int e = blockIdx.x*8 + (threadIdx.x >> 5);
    if (e >= EE) return;
    int lane = threadIdx.x & 31;
    int4 ii = *(const int4*)(info + (size_t)e*4);
    int src = ii.x, k1 = ii.y, dst = ii.z, k2 = ii.w;
    float s = g_sig[(size_t)k1*NPIX + src] + g_sig[(size_t)k2*NPIX + dst];
    s = fminf(5.f, fmaxf(-5.f, s));
    float a = expf(s) * msk[e];
    if (a != 0.f){
        const float4* xr = (const float4*)(g_Xrm + (size_t)src*CC);
        float* xa = g_XA + (size_t)dst*CC;
        int c0 = lane*8;                       // 8 floats per lane
        float4 p = xr[lane*2], q = xr[lane*2+1];
        red4(&xa[c0],   p.x*a, p.y*a, p.z*a, p.w*a);
        red4(&xa[c0+4], q.x*a, q.y*a, q.z*a, q.w*a);
        if (lane == 0) atomicAdd(&g_Asum[dst], a);
    }
}

// ---------------- X_trans = XA/(Asum+eps), in place; accumulate bn1d stats ----------------
__global__ void k_xtrans(){
    int c = threadIdx.x;  // 256
    float s = 0.f, s2 = 0.f;
    for (int r = blockIdx.x; r < NPIX; r += gridDim.x){
        float d = g_Asum[r] + 1e-5f;
        float v = g_XA[(size_t)r*CC + c] / d;
        g_XA[(size_t)r*CC + c] = v;
        s += v; s2 += v*v;
    }
    atomicAdd(&g_stats[c],      (double)s);
    atomicAdd(&g_stats[1024+c], (double)s2);
}

// ---------------- A[c][n] += bn(X_trans)[n][c]  (transposed add) ----------------
__global__ void k_transadd(){
    __shared__ float t[32][33];
    int n0 = blockIdx.x*32, c0 = blockIdx.y*32;
    for (int i = threadIdx.y; i < 32; i += 8)
        t[i][threadIdx.x] = g_XA[(size_t)(n0+i)*CC + c0 + threadIdx.x];
    __syncthreads();
    for (int i = threadIdx.y; i < 32; i += 8){
        int c = c0 + i, n = n0 + threadIdx.x;
        g_A[(size_t)c*NPIX + n] += t[threadIdx.x][i]*g_ss[c] + g_ss[1024+c];
    }
}

// ---------------- out[n][c] = bn(T)[c][n] + A[c][n] ----------------
__global__ void k_finalout(float* __restrict__ out){
    __shared__ float t[32][33];
    int n0 = blockIdx.x*32, c0 = blockIdx.y*32;
    for (int i = threadIdx.y; i < 32; i += 8){
        int c = c0 + i, n = n0 + threadIdx.x;
        t[i][threadIdx.x] = g_T[(size_t)c*NPIX + n]*g_ss[c] + g_ss[1024+c]
                          + g_A[(size_t)c*NPIX + n];
    }
    __syncthreads();
    for (int i = threadIdx.y; i < 32; i += 8)
        out[(size_t)(n0+i)*CC + c0 + threadIdx.x] = t[threadIdx.x][i];
}

// ---------------- host ----------------
extern "C" void kernel_launch(void* const* d_in, const int* in_sizes, int n_in,
                              void* d_out, int out_size){
    const float* X      = (const float*)d_in[0];
    const int*   Info   = (const int*)d_in[1];      // int32 (see k_edge note)
    const float* msk    = (const float*)d_in[2];
    const float* ppm_w0 = (const float*)d_in[3];
    const float* ppm_g0 = (const float*)d_in[4];
    const float* ppm_b0 = (const float*)d_in[5];
    const float* ppm_w1 = (const float*)d_in[6];
    const float* ppm_g1 = (const float*)d_in[7];
    const float* ppm_b1 = (const float*)d_in[8];
    const float* f1w0   = (const float*)d_in[9];
    const float* f1g0   = (const float*)d_in[10];
    const float* f1b0   = (const float*)d_in[11];
    const float* f1w1   = (const float*)d_in[12];
    const float* f1g1   = (const float*)d_in[13];
    const float* f1b1   = (const float*)d_in[14];
    const float* dw1    = (const float*)d_in[15];
    const float* db1    = (const float*)d_in[16];
    const float* dw2    = (const float*)d_in[17];
    const float* db2    = (const float*)d_in[18];
    const float* bng    = (const float*)d_in[19];
    const float* bnb    = (const float*)d_in[20];
    const float* f2w0   = (const float*)d_in[21];
    const float* f2g0   = (const float*)d_in[22];
    const float* f2b0   = (const float*)d_in[23];
    const float* f2w1   = (const float*)d_in[24];
    const float* f2g1   = (const float*)d_in[25];
    const float* f2b1   = (const float*)d_in[26];

    float *A,*T,*U,*Hh,*Xrm,*Sig,*Asum,*XA,*Hid;
    uint32_t *Wtf;
    cudaGetSymbolAddress((void**)&A,    g_A);
    cudaGetSymbolAddress((void**)&T,    g_T);
    cudaGetSymbolAddress((void**)&U,    g_U);
    cudaGetSymbolAddress((void**)&Hh,   g_h);
    cudaGetSymbolAddress((void**)&Xrm,  g_Xrm);
    cudaGetSymbolAddress((void**)&Sig,  g_sig);
    cudaGetSymbolAddress((void**)&Asum, g_Asum);
    cudaGetSymbolAddress((void**)&XA,   g_XA);
    cudaGetSymbolAddress((void**)&Hid,  g_hid);
    cudaGetSymbolAddress((void**)&Wtf,  g_Wtf);

    dim3 b32x8(32,8), b1024(32,32), b8x32(8,32);
    dim3 gT17(WW/64, HH/32, CC);           // (3,6,256)
    dim3 gTile(WW/32, HH/32, CC);          // (6,6,256)
    dim3 gTrans(NPIX/32, CC/32);           // (1152,8)
    dim3 gM(NPIX/128, 2);                  // (288,2)  M=256
    dim3 gMK(NPIX/128, 3);                 // (288,3)  M=289 (padded W rows to 384)

    // keep launch order: dw17 remains at the ncu-profiled slot
    k_zero_stats<<<1,1024>>>();                                    // 0
    k_wconv<<<(WT_TOTAL+255)/256,256>>>(ppm_w1, f1w0, f1w1, dw1, dw2, f2w1); // 1
    k_nc2cn<<<gTrans, b32x8>>>(X, A);                              // 2
    k_dw17<<<gT17, b8x32>>>(A, ppm_w0, T);                         // 3 <- profiled
    k_bnfin<<<1,256>>>(ppm_g0, ppm_b0, 256);                       // 4
    k_mma<true,true,false,false,true><<<gM,256>>>(Wtf+OFF_PPM1, T, U, 256, 256, nullptr);
    k_bnfin<<<1,256>>>(ppm_g1, ppm_b1, 256);
    k_resid<<<CC*NPIX/4/256,256>>>(A, U);

    // ffn1
    k_mma<false,true,false,false,true><<<gM,256>>>(Wtf+OFF_F1W0, A, T, 256, 256, nullptr);
    k_bnfin<<<1,256>>>(f1g0, f1b0, 256);
    k_mma<true,true,false,false,true><<<gM,256>>>(Wtf+OFF_F1W1, T, U, 256, 256, nullptr);
    k_bnfin<<<1,256>>>(f1g1, f1b1, 256);
    k_resid<<<CC*NPIX/4/256,256>>>(A, U);      // A = Xn

    // Xn row-major copy for edge gather
    k_cn2nc<<<gTrans, b32x8>>>(A, Xrm);

    // dis: h = leaky(W1 @ Xn + b1); sig = W2 @ h + b2
    k_mma<false,false,true,true,false><<<gM,256>>>(Wtf+OFF_DW1, A, Hh, 256, 256, db1);
    k_mma<false,false,true,false,false><<<gMK,256>>>(Wtf+OFF_DW2, Hh, Sig, KK, 256, db2);

    // edge aggregation
    k_zero<<<(NPIX*CC+255)/256,256>>>(XA, NPIX*CC);
    k_zero<<<(NPIX+255)/256,256>>>(Asum, NPIX);
    k_edge<<<EE/8,256>>>(Info, msk);
    k_xtrans<<<288,256>>>();
    k_bnfin<<<1,256>>>(bng, bnb, 256);
    k_transadd<<<gTrans, b32x8>>>();           // A = Xn + bn1d(X_trans)

    // ffn2
    k_dw3<<<gTile, b1024>>>(A, f2w0, Hid);
    k_bnfin<<<4,256>>>(f2g0, f2b0, 1024);
    k_mma<true,true,false,false,true><<<gM,256>>>(Wtf+OFF_F2W1, Hid, T, 256, 1024, nullptr);
    k_bnfin<<<1,256>>>(f2g1, f2b1, 256);

    k_finalout<<<gTrans, b32x8>>>((float*)d_out);
}

// round 13
// speedup vs baseline: 2.6137x; 1.0364x over previous
#include <cuda_runtime.h>
#include <math.h>
#include <stdint.h>

#define HH 192
#define WW 192
#define NPIX (HH*WW)        // 36864
#define CC 256
#define EE 294912
#define KK 289
#define SLOPE 0.01f
#define EPSV 1e-5f

// tf32 weight buffer offsets (words)
#define OFF_PPM1 0
#define OFF_F1W0 65536
#define OFF_F1W1 131072
#define OFF_DW1  196608
#define OFF_DW2  262144          // padded to 384 rows x 256
#define OFF_F2W1 360448          // 256 x 1024
#define WT_TOTAL 622592

// ---------------- scratch (device globals; no allocation) ----------------
__device__ float g_A[CC*NPIX];        // main activation, channel-major [C][N]
__device__ float g_T[CC*NPIX];        // temp
__device__ float g_U[CC*NPIX];        // temp
__device__ float g_h[CC*NPIX];        // dis hidden
__device__ float g_Xrm[NPIX*CC];      // Xn row-major for edge gather
__device__ float g_sig[KK*NPIX];      // signal [K][N]
__device__ float g_Asum[NPIX];
__device__ float g_XA[NPIX*CC];       // row-major scatter target / X_trans
__device__ float g_hid[4*CC*NPIX];    // ffn2 hidden, 1024 channels
__device__ double g_stats[2048];      // per-channel sum (0..1023), sumsq (1024..2047)
__device__ float  g_ss[2048];         // per-channel scale (0..1023), shift (1024..2047)
__device__ uint32_t g_Wtf[WT_TOTAL];  // pre-converted tf32 weights

__device__ __forceinline__ float lk(float x){ return x >= 0.f ? x : SLOPE*x; }
__device__ __forceinline__ uint32_t f2tf(float f){
    uint32_t u; asm("cvt.rna.tf32.f32 %0, %1;" : "=r"(u) : "f"(f)); return u;
}
__device__ __forceinline__ void cpasync16(uint32_t dst, const void* src){
    asm volatile("cp.async.ca.shared.global [%0], [%1], 16;" :: "r"(dst), "l"(src));
}
__device__ __forceinline__ void red4(float* p, float a, float b, float c, float d){
    asm volatile("red.global.add.v4.f32 [%0], {%1,%2,%3,%4};"
                 :: "l"(p), "f"(a), "f"(b), "f"(c), "f"(d) : "memory");
}

// ---------------- utility kernels ----------------
__global__ void k_zero(float* __restrict__ p, int n){
    int i = blockIdx.x*blockDim.x + threadIdx.x;
    if (i < n) p[i] = 0.f;
}
__global__ void k_zero_stats(){
    int i = threadIdx.x;            // 1024 threads
    g_stats[i] = 0.0; g_stats[i+1024] = 0.0;
}

// convert all GEMM weights to tf32 bit patterns (dw2 padded to 384 rows)
__global__ void k_wconv(const float* __restrict__ p1, const float* __restrict__ p2,
                        const float* __restrict__ p3, const float* __restrict__ p4,
                        const float* __restrict__ p5, const float* __restrict__ p6){
    int i = blockIdx.x*256 + threadIdx.x;
    if (i >= WT_TOTAL) return;
    uint32_t v;
    if      (i < OFF_F1W0) v = f2tf(p1[i]);
    else if (i < OFF_F1W1) v = f2tf(p2[i-OFF_F1W0]);
    else if (i < OFF_DW1)  v = f2tf(p3[i-OFF_F1W1]);
    else if (i < OFF_DW2)  v = f2tf(p4[i-OFF_DW1]);
    else if (i < OFF_F2W1){ int j = i-OFF_DW2; v = (j < KK*CC) ? f2tf(p5[j]) : 0u; }
    else                   v = f2tf(p6[i-OFF_F2W1]);
    g_Wtf[i] = v;
}

// BN finalize: scale/shift from stats, reset stats.
__global__ void k_bnfin(const float* __restrict__ g, const float* __restrict__ b, int nch){
    int c = blockIdx.x*blockDim.x + threadIdx.x;
    if (c >= nch) return;
    double s = g_stats[c], s2 = g_stats[1024+c];
    float m   = (float)(s  / (double)NPIX);
    float var = (float)(s2 / (double)NPIX) - m*m;
    float sc  = g[c] * rsqrtf(var + EPSV);
    g_ss[c]      = sc;
    g_ss[1024+c] = b[c] - m*sc;
    g_stats[c] = 0.0; g_stats[1024+c] = 0.0;
}

// (N,C) -> (C,N)
__global__ void k_nc2cn(const float* __restrict__ in, float* __restrict__ out){
    __shared__ float t[32][33];
    int n0 = blockIdx.x*32, c0 = blockIdx.y*32;
    for (int i = threadIdx.y; i < 32; i += 8)
        t[i][threadIdx.x] = in[(size_t)(n0+i)*CC + c0 + threadIdx.x];
    __syncthreads();
    for (int i = threadIdx.y; i < 32; i += 8)
        out[(size_t)(c0+i)*NPIX + n0 + threadIdx.x] = t[threadIdx.x][i];
}

// ---------------- depthwise 17x17, 8 outputs/thread, vectorized weight loads ----------------
// block (8,32)=256; output tile 64(x) x 32(y); thread -> x = tx*4+{0..3} and tx*4+32+{0..3}
__global__ void __launch_bounds__(256) k_dw17(const float* __restrict__ A,
                                              const float* __restrict__ w0,
                                              float* __restrict__ Om){
    __shared__ __align__(16) float sIn[48][80];
    __shared__ __align__(16) float sW[17][20];   // padded rows: 4xLDS.128 + 1 scalar per ky
    __shared__ float sRedS[8], sRedQ[8];
    int c  = blockIdx.z;
    int x0 = blockIdx.x*64, y0 = blockIdx.y*32;
    const float* Ac = A + (size_t)c*NPIX;
    int tx = threadIdx.x, ty = threadIdx.y;
    int tid = ty*8 + tx;
    for (int i = tid; i < 289; i += 256) sW[i/17][i%17] = w0[c*289 + i];
    for (int i = tid; i < 48*80; i += 256){
        int ly = i/80, lx = i%80;
        int gx = x0 - 8 + lx, gy = y0 - 8 + ly;
        float v = 0.f;
        if ((unsigned)gx < WW && (unsigned)gy < HH) v = lk(Ac[gy*WW + gx]);
        sIn[ly][lx] = v;
    }
    __syncthreads();
    float a0=0.f,a1=0.f,a2=0.f,a3=0.f,a4=0.f,a5=0.f,a6=0.f,a7=0.f;
    #pragma unroll
    for (int ky = 0; ky < 17; ky++){
        const float* rp = &sIn[ty+ky][tx*4];
        float u[20], v[20];
        #pragma unroll
        for (int q = 0; q < 5; q++) *(float4*)&u[q*4] = *(const float4*)&rp[q*4];
        #pragma unroll
        for (int q = 0; q < 5; q++) *(float4*)&v[q*4] = *(const float4*)&rp[32+q*4];
        #pragma unroll
        for (int q = 0; q < 4; q++){
            float4 wq = *(const float4*)&sW[ky][q*4];
            int k = q*4;
            a0 += u[k]*wq.x;   a1 += u[k+1]*wq.x; a2 += u[k+2]*wq.x; a3 += u[k+3]*wq.x;
            a4 += v[k]*wq.x;   a5 += v[k+1]*wq.x; a6 += v[k+2]*wq.x; a7 += v[k+3]*wq.x;
            a0 += u[k+1]*wq.y; a1 += u[k+2]*wq.y; a2 += u[k+3]*wq.y; a3 += u[k+4]*wq.y;
            a4 += v[k+1]*wq.y; a5 += v[k+2]*wq.y; a6 += v[k+3]*wq.y; a7 += v[k+4]*wq.y;
            a0 += u[k+2]*wq.z; a1 += u[k+3]*wq.z; a2 += u[k+4]*wq.z; a3 += u[k+5]*wq.z;
            a4 += v[k+2]*wq.z; a5 += v[k+3]*wq.z; a6 += v[k+4]*wq.z; a7 += v[k+5]*wq.z;
            a0 += u[k+3]*wq.w; a1 += u[k+4]*wq.w; a2 += u[k+5]*wq.w; a3 += u[k+6]*wq.w;
            a4 += v[k+3]*wq.w; a5 += v[k+4]*wq.w; a6 += v[k+5]*wq.w; a7 += v[k+6]*wq.w;
        }
        float w16 = sW[ky][16];
        a0 += u[16]*w16; a1 += u[17]*w16; a2 += u[18]*w16; a3 += u[19]*w16;
        a4 += v[16]*w16; a5 += v[17]*w16; a6 += v[18]*w16; a7 += v[19]*w16;
    }
    int n = (y0+ty)*WW + x0 + tx*4;
    *(float4*)&Om[(size_t)c*NPIX + n]      = make_float4(a0,a1,a2,a3);
    *(float4*)&Om[(size_t)c*NPIX + n + 32] = make_float4(a4,a5,a6,a7);
    float s  = a0+a1+a2+a3+a4+a5+a6+a7;
    float s2 = a0*a0+a1*a1+a2*a2+a3*a3+a4*a4+a5*a5+a6*a6+a7*a7;
    #pragma unroll
    for (int o = 16; o > 0; o >>= 1){
        s  += __shfl_down_sync(0xffffffffu, s,  o);
        s2 += __shfl_down_sync(0xffffffffu, s2, o);
    }
    if ((tid & 31) == 0){ sRedS[tid>>5] = s; sRedQ[tid>>5] = s2; }
    __syncthreads();
    if (tid < 8){
        s = sRedS[tid]; s2 = sRedQ[tid];
        #pragma unroll
        for (int o = 4; o > 0; o >>= 1){
            s  += __shfl_down_sync(0xffu, s,  o, 8);
            s2 += __shfl_down_sync(0xffu, s2, o, 8);
        }
        if (tid == 0){
            atomicAdd(&g_stats[c],      (double)s);
            atomicAdd(&g_stats[1024+c], (double)s2);
        }
    }
}

// ---------------- depthwise 3x3 with channel multiplier 4, block-reduced stats ----------------
__global__ void __launch_bounds__(1024) k_dw3(const float* __restrict__ A,
                                              const float* __restrict__ w0,
                                              float* __restrict__ Om){
    __shared__ float sIn[34][34];
    __shared__ float sW[36];
    __shared__ float rS[4][32], rQ[4][32];
    int c  = blockIdx.z;
    int x0 = blockIdx.x*32, y0 = blockIdx.y*32;
    const float* Ac = A + (size_t)c*NPIX;
    int tid = threadIdx.y*32 + threadIdx.x;
    int wid = tid >> 5, lane = tid & 31;
    if (tid < 36) sW[tid] = w0[c*36 + tid];
    for (int i = tid; i < 34*34; i += 1024){
        int ly = i/34, lx = i%34;
        int gx = x0 - 1 + lx, gy = y0 - 1 + ly;
        float v = 0.f;
        if ((unsigned)gx < WW && (unsigned)gy < HH) v = lk(Ac[gy*WW + gx]);
        sIn[ly][lx] = v;
    }
    __syncthreads();
    float pix[9];
    #pragma unroll
    for (int dy = 0; dy < 3; dy++)
        #pragma unroll
        for (int dx = 0; dx < 3; dx++)
            pix[dy*3+dx] = sIn[threadIdx.y+dy][threadIdx.x+dx];
    int n = (y0+threadIdx.y)*WW + x0 + threadIdx.x;
    #pragma unroll
    for (int j = 0; j < 4; j++){
        float acc = 0.f;
        #pragma unroll
        for (int q = 0; q < 9; q++) acc += pix[q] * sW[j*9+q];
        Om[(size_t)(4*c+j)*NPIX + n] = acc;
        float s = acc, s2 = acc*acc;
        #pragma unroll
        for (int o = 16; o > 0; o >>= 1){
            s  += __shfl_down_sync(0xffffffffu, s,  o);
            s2 += __shfl_down_sync(0xffffffffu, s2, o);
        }
        if (lane == 0){ rS[j][wid] = s; rQ[j][wid] = s2; }
    }
    __syncthreads();
    if (wid < 4){
        float s = rS[wid][lane], s2 = rQ[wid][lane];
        #pragma unroll
        for (int o = 16; o > 0; o >>= 1){
            s  += __shfl_down_sync(0xffffffffu, s,  o);
            s2 += __shfl_down_sync(0xffffffffu, s2, o);
        }
        if (lane == 0){
            atomicAdd(&g_stats[4*c+wid],      (double)s);
            atomicAdd(&g_stats[1024+4*c+wid], (double)s2);
        }
    }
}

// ---------------- TF32 tensor-core GEMM, double-buffered, cp.async W path ----------------
// Grid: x = m-tiles (fast-varying -> adjacent CTAs share the B tile in L2), y = n-tiles.
#define MMA_TF32(d, a, b) asm volatile( \
  "mma.sync.aligned.m16n8k8.row.col.f32.tf32.tf32.f32 " \
  "{%0,%1,%2,%3}, {%4,%5,%6,%7}, {%8,%9}, {%0,%1,%2,%3};" \
  : "+f"(d[0]), "+f"(d[1]), "+f"(d[2]), "+f"(d[3]) \
  : "r"(a[0]), "r"(a[1]), "r"(a[2]), "r"(a[3]), "r"(b[0]), "r"(b[1]))

#define AS_STRIDE 20   // 16 + 4 pad
#define BS_STRIDE 136  // 128 + 8 pad

template<bool TRANS, bool INLK, bool BIAS, bool OUTLK, bool STATS>
__global__ void __launch_bounds__(256,2) k_mma(const uint32_t* __restrict__ Wm,
                                               const float* __restrict__ Am,
                                               float* __restrict__ Om,
                                               int M, int Kc,
                                               const float* __restrict__ bias){
    __shared__ __align__(16) uint32_t As[2][128*AS_STRIDE];
    __shared__ __align__(16) uint32_t Bs[2][16*BS_STRIDE];
    const int tid  = threadIdx.x;
    const int lane = tid & 31;
    const int wid  = tid >> 5;
    const int gid  = lane >> 2, ctg = lane & 3;
    const int wm   = wid & 1,  wn  = wid >> 1;
    const int m0 = blockIdx.x*128, n0 = blockIdx.y*128;

    const int mA  = tid >> 1;          // 0..127
    const int kqA = (tid & 1)*8;       // 0 or 8
    const int kB  = wid;               // 0..7
    const int nB  = lane*4;

    float acc[4][4][4];
    #pragma unroll
    for (int i = 0; i < 4; i++)
        #pragma unroll
        for (int j = 0; j < 4; j++)
            #pragma unroll
            for (int q = 0; q < 4; q++) acc[i][j][q] = 0.f;

    float4 ba, bb;

    auto WASYNC = [&](int p, int k0){
        const uint32_t* wp = &Wm[(size_t)(m0+mA)*Kc + k0 + kqA];
        uint32_t d0 = (uint32_t)__cvta_generic_to_shared(&As[p][mA*AS_STRIDE + kqA]);
        cpasync16(d0, wp);
        cpasync16(d0 + 16, wp + 4);
    };
    auto LOADB = [&](int k0){
        ba = *(const float4*)&Am[(size_t)(k0+kB)*NPIX   + n0 + nB];
        bb = *(const float4*)&Am[(size_t)(k0+kB+8)*NPIX + n0 + nB];
    };
    auto STOREB = [&](int p, int k0){
        float4 v0 = ba, v1 = bb;
        if (TRANS){
            float sc0 = g_ss[k0+kB],   sh0 = g_ss[1024+k0+kB];
            float sc1 = g_ss[k0+kB+8], sh1 = g_ss[1024+k0+kB+8];
            v0.x = v0.x*sc0+sh0; v0.y = v0.y*sc0+sh0; v0.z = v0.z*sc0+sh0; v0.w = v0.w*sc0+sh0;
            v1.x = v1.x*sc1+sh1; v1.y = v1.y*sc1+sh1; v1.z = v1.z*sc1+sh1; v1.w = v1.w*sc1+sh1;
        }
        if (INLK){
            v0.x = lk(v0.x); v0.y = lk(v0.y); v0.z = lk(v0.z); v0.w = lk(v0.w);
            v1.x = lk(v1.x); v1.y = lk(v1.y); v1.z = lk(v1.z); v1.w = lk(v1.w);
        }
        *(uint4*)&Bs[p][kB*BS_STRIDE + nB] =
            make_uint4(f2tf(v0.x), f2tf(v0.y), f2tf(v0.z), f2tf(v0.w));
        *(uint4*)&Bs[p][(kB+8)*BS_STRIDE + nB] =
            make_uint4(f2tf(v1.x), f2tf(v1.y), f2tf(v1.z), f2tf(v1.w));
    };
    auto COMPUTE = [&](int p){
        #pragma unroll
        for (int ks = 0; ks < 16; ks += 8){
            uint32_t a[4][4], b[4][2];
            #pragma unroll
            for (int mi = 0; mi < 4; mi++){
                int rb = wm*64 + mi*16 + gid;
                a[mi][0] = As[p][rb*AS_STRIDE     + ks+ctg];
                a[mi][1] = As[p][(rb+8)*AS_STRIDE + ks+ctg];
                a[mi][2] = As[p][rb*AS_STRIDE     + ks+ctg+4];
                a[mi][3] = As[p][(rb+8)*AS_STRIDE + ks+ctg+4];
            }
            #pragma unroll
            for (int ni = 0; ni < 4; ni++){
                int cb = wn*32 + ni*8 + gid;
                b[ni][0] = Bs[p][(ks+ctg)*BS_STRIDE   + cb];
                b[ni][1] = Bs[p][(ks+ctg+4)*BS_STRIDE + cb];
            }
            #pragma unroll
            for (int mi = 0; mi < 4; mi++)
                #pragma unroll
                for (int ni = 0; ni < 4; ni++)
                    MMA_TF32(acc[mi][ni], a[mi], b[ni]);
        }
    };

    const int nT = Kc >> 4;
    WASYNC(0, 0);
    asm volatile("cp.async.commit_group;");
    LOADB(0);
    STOREB(0, 0);
    asm volatile("cp.async.wait_group 0;" ::: "memory");
    __syncthreads();
    for (int it = 1; it < nT; it++){
        WASYNC(it&1, it*16);
        asm volatile("cp.async.commit_group;");
        LOADB(it*16);
        COMPUTE((it-1)&1);
        STOREB(it&1, it*16);
        asm volatile("cp.async.wait_group 0;" ::: "memory");
        __syncthreads();
    }
    COMPUTE((nT-1)&1);

    // --- epilogue ---
    #pragma unroll
    for (int mi = 0; mi < 4; mi++){
        int r0 = m0 + wm*64 + mi*16 + gid;
        int r1 = r0 + 8;
        bool v0r = r0 < M, v1r = r1 < M;
        float b0 = 0.f, b1 = 0.f;
        if (BIAS){ if (v0r) b0 = bias[r0]; if (v1r) b1 = bias[r1]; }
        float s0 = 0.f, q0 = 0.f, s1 = 0.f, q1 = 0.f;
        #pragma unroll
        for (int ni = 0; ni < 4; ni++){
            int cix = n0 + wn*32 + ni*8 + 2*ctg;
            float v0 = acc[mi][ni][0], v1 = acc[mi][ni][1];
            float v2 = acc[mi][ni][2], v3 = acc[mi][ni][3];
            if (BIAS){ v0 += b0; v1 += b0; v2 += b1; v3 += b1; }
            if (OUTLK){ v0 = lk(v0); v1 = lk(v1); v2 = lk(v2); v3 = lk(v3); }
            if (v0r) *(float2*)&Om[(size_t)r0*NPIX + cix] = make_float2(v0, v1);
            if (v1r) *(float2*)&Om[(size_t)r1*NPIX + cix] = make_float2(v2, v3);
            if (STATS){
                s0 += v0+v1; q0 += v0*v0+v1*v1;
                s1 += v2+v3; q1 += v2*v2+v3*v3;
            }
        }
        if (STATS){
            s0 += __shfl_down_sync(0xffffffffu, s0, 2, 4); s0 += __shfl_down_sync(0xffffffffu, s0, 1, 4);
            q0 += __shfl_down_sync(0xffffffffu, q0, 2, 4); q0 += __shfl_down_sync(0xffffffffu, q0, 1, 4);
            s1 += __shfl_down_sync(0xffffffffu, s1, 2, 4); s1 += __shfl_down_sync(0xffffffffu, s1, 1, 4);
            q1 += __shfl_down_sync(0xffffffffu, q1, 2, 4); q1 += __shfl_down_sync(0xffffffffu, q1, 1, 4);
            if (ctg == 0){
                if (v0r){ atomicAdd(&g_stats[r0], (double)s0); atomicAdd(&g_stats[1024+r0], (double)q0); }
                if (v1r){ atomicAdd(&g_stats[r1], (double)s1); atomicAdd(&g_stats[1024+r1], (double)q1); }
            }
        }
    }
}

// ---------------- residual: A += U*scale[c]+shift[c] ----------------
__global__ void k_resid(float* __restrict__ A, const float* __restrict__ U){
    int i = blockIdx.x*blockDim.x + threadIdx.x;     // float4 index
    int c = i / (NPIX/4);
    float sc = g_ss[c], sh = g_ss[1024+c];
    float4 u = ((const float4*)U)[i];
    float4 a = ((float4*)A)[i];
    a.x += u.x*sc+sh; a.y += u.y*sc+sh; a.z += u.z*sc+sh; a.w += u.w*sc+sh;
    ((float4*)A)[i] = a;
}

// ---------------- fused residual + transpose: A += bn(U); Xrm = A^T ----------------
__global__ void k_resid2t(float* __restrict__ A, const float* __restrict__ U,
                          float* __restrict__ Xrm){
    __shared__ float t[32][33];
    int n0 = blockIdx.x*32, c0 = blockIdx.y*32;
    for (int i = threadIdx.y; i < 32; i += 8){
        int c = c0 + i;
        size_t ix = (size_t)c*NPIX + n0 + threadIdx.x;
        float v = g_A[ix]*0.f + A[ix] + U[ix]*g_ss[c] + g_ss[1024+c];
        A[ix] = v;
        t[i][threadIdx.x] = v;
    }
    __syncthreads();
    for (int i = threadIdx.y; i < 32; i += 8)
        Xrm[(size_t)(n0+i)*CC + c0 + threadIdx.x] = t[threadIdx.x][i];
}

// ---------------- edge kernel: one warp per edge, vector red.v4 scatter ----------------
// NOTE: InfoIdx is int32 (JAX x64 disabled -> astype(int64) is a no-op to int32)
__global__ void k_edge(const int* __restrict__ info, const float* __restrict__ msk){
    int e = blockIdx.x*8 + (threadIdx.x >> 5);
    if (e >= EE) return;
    int lane = threadIdx.x & 31;
    int4 ii = *(const int4*)(info + (size_t)e*4);
    int src = ii.x, k1 = ii.y, dst = ii.z, k2 = ii.w;
    float s = g_sig[(size_t)k1*NPIX + src] + g_sig[(size_t)k2*NPIX + dst];
    s = fminf(5.f, fmaxf(-5.f, s));
    float a = expf(s) * msk[e];
    if (a != 0.f){
        const float4* xr = (const float4*)(g_Xrm + (size_t)src*CC);
        float* xa = g_XA + (size_t)dst*CC;
        int c0 = lane*8;                       // 8 floats per lane
        float4 p = xr[lane*2], q = xr[lane*2+1];
        red4(&xa[c0],   p.x*a, p.y*a, p.z*a, p.w*a);
        red4(&xa[c0+4], q.x*a, q.y*a, q.z*a, q.w*a);
        if (lane == 0) atomicAdd(&g_Asum[dst], a);
    }
}

// ---------------- X_trans = XA/(Asum+eps), in place; accumulate bn1d stats ----------------
__global__ void k_xtrans(){
    int c = threadIdx.x;  // 256
    float s = 0.f, s2 = 0.f;
    for (int r = blockIdx.x; r < NPIX; r += gridDim.x){
        float d = g_Asum[r] + 1e-5f;
        float v = g_XA[(size_t)r*CC + c] / d;
        g_XA[(size_t)r*CC + c] = v;
        s += v; s2 += v*v;
    }
    atomicAdd(&g_stats[c],      (double)s);
    atomicAdd(&g_stats[1024+c], (double)s2);
}

// ---------------- A[c][n] += bn(X_trans)[n][c]  (transposed add) ----------------
__global__ void k_transadd(){
    __shared__ float t[32][33];
    int n0 = blockIdx.x*32, c0 = blockIdx.y*32;
    for (int i = threadIdx.y; i < 32; i += 8)
        t[i][threadIdx.x] = g_XA[(size_t)(n0+i)*CC + c0 + threadIdx.x];
    __syncthreads();
    for (int i = threadIdx.y; i < 32; i += 8){
        int c = c0 + i, n = n0 + threadIdx.x;
        g_A[(size_t)c*NPIX + n] += t[threadIdx.x][i]*g_ss[c] + g_ss[1024+c];
    }
}

// ---------------- out[n][c] = bn(T)[c][n] + A[c][n] ----------------
__global__ void k_finalout(float* __restrict__ out){
    __shared__ float t[32][33];
    int n0 = blockIdx.x*32, c0 = blockIdx.y*32;
    for (int i = threadIdx.y; i < 32; i += 8){
        int c = c0 + i, n = n0 + threadIdx.x;
        t[i][threadIdx.x] = g_T[(size_t)c*NPIX + n]*g_ss[c] + g_ss[1024+c]
                          + g_A[(size_t)c*NPIX + n];
    }
    __syncthreads();
    for (int i = threadIdx.y; i < 32; i += 8)
        out[(size_t)(n0+i)*CC + c0 + threadIdx.x] = t[threadIdx.x][i];
}

// ---------------- host ----------------
extern "C" void kernel_launch(void* const* d_in, const int* in_sizes, int n_in,
                              void* d_out, int out_size){
    const float* X      = (const float*)d_in[0];
    const int*   Info   = (const int*)d_in[1];      // int32 (see k_edge note)
    const float* msk    = (const float*)d_in[2];
    const float* ppm_w0 = (const float*)d_in[3];
    const float* ppm_g0 = (const float*)d_in[4];
    const float* ppm_b0 = (const float*)d_in[5];
    const float* ppm_w1 = (const float*)d_in[6];
    const float* ppm_g1 = (const float*)d_in[7];
    const float* ppm_b1 = (const float*)d_in[8];
    const float* f1w0   = (const float*)d_in[9];
    const float* f1g0   = (const float*)d_in[10];
    const float* f1b0   = (const float*)d_in[11];
    const float* f1w1   = (const float*)d_in[12];
    const float* f1g1   = (const float*)d_in[13];
    const float* f1b1   = (const float*)d_in[14];
    const float* dw1    = (const float*)d_in[15];
    const float* db1    = (const float*)d_in[16];
    const float* dw2    = (const float*)d_in[17];
    const float* db2    = (const float*)d_in[18];
    const float* bng    = (const float*)d_in[19];
    const float* bnb    = (const float*)d_in[20];
    const float* f2w0   = (const float*)d_in[21];
    const float* f2g0   = (const float*)d_in[22];
    const float* f2b0   = (const float*)d_in[23];
    const float* f2w1   = (const float*)d_in[24];
    const float* f2g1   = (const float*)d_in[25];
    const float* f2b1   = (const float*)d_in[26];

    float *A,*T,*U,*Hh,*Xrm,*Sig,*Asum,*XA,*Hid;
    uint32_t *Wtf;
    cudaGetSymbolAddress((void**)&A,    g_A);
    cudaGetSymbolAddress((void**)&T,    g_T);
    cudaGetSymbolAddress((void**)&U,    g_U);
    cudaGetSymbolAddress((void**)&Hh,   g_h);
    cudaGetSymbolAddress((void**)&Xrm,  g_Xrm);
    cudaGetSymbolAddress((void**)&Sig,  g_sig);
    cudaGetSymbolAddress((void**)&Asum, g_Asum);
    cudaGetSymbolAddress((void**)&XA,   g_XA);
    cudaGetSymbolAddress((void**)&Hid,  g_hid);
    cudaGetSymbolAddress((void**)&Wtf,  g_Wtf);

    dim3 b32x8(32,8), b1024(32,32), b8x32(8,32);
    dim3 gT17(WW/64, HH/32, CC);           // (3,6,256)
    dim3 gTile(WW/32, HH/32, CC);          // (6,6,256)
    dim3 gTrans(NPIX/32, CC/32);           // (1152,8)
    dim3 gM(2, NPIX/128);                  // m-tiles fast: B tile L2-reuse
    dim3 gMK(3, NPIX/128);                 // M=289 (padded W rows to 384)

    // keep launch order: dw17 remains at the ncu-profiled slot
    k_zero_stats<<<1,1024>>>();                                    // 0
    k_wconv<<<(WT_TOTAL+255)/256,256>>>(ppm_w1, f1w0, f1w1, dw1, dw2, f2w1); // 1
    k_nc2cn<<<gTrans, b32x8>>>(X, A);                              // 2
    k_dw17<<<gT17, b8x32>>>(A, ppm_w0, T);                         // 3 <- profiled
    k_bnfin<<<1,256>>>(ppm_g0, ppm_b0, 256);                       // 4
    k_mma<true,true,false,false,true><<<gM,256>>>(Wtf+OFF_PPM1, T, U, 256, 256, nullptr);
    k_bnfin<<<1,256>>>(ppm_g1, ppm_b1, 256);
    k_resid<<<CC*NPIX/4/256,256>>>(A, U);

    // ffn1
    k_mma<false,true,false,false,true><<<gM,256>>>(Wtf+OFF_F1W0, A, T, 256, 256, nullptr);
    k_bnfin<<<1,256>>>(f1g0, f1b0, 256);
    k_mma<true,true,false,false,true><<<gM,256>>>(Wtf+OFF_F1W1, T, U, 256, 256, nullptr);
    k_bnfin<<<1,256>>>(f1g1, f1b1, 256);
    k_resid2t<<<gTrans, b32x8>>>(A, U, Xrm);   // A = Xn; Xrm = Xn row-major (fused)

    // dis: h = leaky(W1 @ Xn + b1); sig = W2 @ h + b2
    k_mma<false,false,true,true,false><<<gM,256>>>(Wtf+OFF_DW1, A, Hh, 256, 256, db1);
    k_mma<false,false,true,false,false><<<gMK,256>>>(Wtf+OFF_DW2, Hh, Sig, KK, 256, db2);

    // edge aggregation
    k_zero<<<(NPIX*CC+255)/256,256>>>(XA, NPIX*CC);
    k_zero<<<(NPIX+255)/256,256>>>(Asum, NPIX);
    k_edge<<<EE/8,256>>>(Info, msk);
    k_xtrans<<<288,256>>>();
    k_bnfin<<<1,256>>>(bng, bnb, 256);
    k_transadd<<<gTrans, b32x8>>>();           // A = Xn + bn1d(X_trans)

    // ffn2
    k_dw3<<<gTile, b1024>>>(A, f2w0, Hid);
    k_bnfin<<<4,256>>>(f2g0, f2b0, 1024);
    k_mma<true,true,false,false,true><<<gM,256>>>(Wtf+OFF_F2W1, Hid, T, 256, 1024, nullptr);
    k_bnfin<<<1,256>>>(f2g1, f2b1, 256);

    k_finalout<<<gTrans, b32x8>>>((float*)d_out);
}